// round 4
// baseline (speedup 1.0000x reference)
#include <cuda_runtime.h>
#include <math.h>

// ============================================================================
// FamNet pipeline, fp32, packed-f32x2 (FFMA2) register-tiled convolutions.
// ============================================================================

#define NB 2
#define NP 3

typedef unsigned long long ull;

__device__ __forceinline__ ull pack2(float a, float b) {
    ull r; asm("mov.b64 %0, {%1, %2};" : "=l"(r) : "f"(a), "f"(b)); return r;
}
__device__ __forceinline__ void fma2(ull& d, ull a, ull b, ull c) {
    asm("fma.rn.f32x2 %0, %1, %2, %3;" : "=l"(d) : "l"(a), "l"(b), "l"(c));
}
__device__ __forceinline__ float2 unpack2(ull v) {
    float2 f; asm("mov.b64 {%0, %1}, %2;" : "=f"(f.x), "=f"(f.y) : "l"(v)); return f;
}

// ---------------- device scratch (no allocations allowed) -------------------
__device__ float g_x1[2 * 64 * 192 * 192];
__device__ float g_x2[2 * 256 * 96 * 96];
__device__ float g_f3[2 * 512 * 48 * 48];
__device__ float g_f4[2 * 1024 * 24 * 24];
__device__ float g_patches[3 * 1024 * 24 * 24];   // stride-24 layout
__device__ float g_pf[3 * 1024 * 32 * 32];        // stride-32 layout
__device__ float g_simtmp[3 * 48 * 48];
__device__ float g_sims[2 * 3 * 6 * 48 * 48];
__device__ float g_r1[6 * 196 * 48 * 48];
__device__ float g_u1[6 * 196 * 96 * 96];
__device__ float g_r2[6 * 128 * 96 * 96];
__device__ float g_u2[6 * 128 * 192 * 192];
__device__ float g_r3[6 * 64 * 192 * 192];
__device__ float g_u3[6 * 64 * 384 * 384];
__device__ float g_r4[6 * 32 * 384 * 384];
__device__ float g_wbuf[1024 * 512 * 9];          // transposed weights [ci][k][co_pad]

// ---------------- box / scale metadata (computed on device) -----------------
__device__ int g_tl[2][2][3][2];
__device__ int g_crop[2][2][3][2];
__device__ int g_PH[2][2], g_PW[2][2];
__device__ int g_PHs[2][2][3], g_PWs[2][2][3];

__global__ void meta_kernel(const float* __restrict__ tlbrs) {
    if (threadIdx.x != 0 || blockIdx.x != 0) return;
    const double scales[3] = {1.0, 0.9, 1.1};
    for (int b = 0; b < NB; b++) {
        for (int L = 0; L < 2; L++) {
            int F = (L == 0) ? 48 : 24;
            float inv = (float)F / 384.0f;
            int maxh = 0, maxw = 0;
            for (int p = 0; p < NP; p++) {
                const float* v = tlbrs + (b * NP + p) * 4;
                float sct = v[0] * inv, scl = v[1] * inv;
                float scb = v[2] * inv, scr = v[3] * inv;
                int top = (int)floorf(sct); if (top < 0) top = 0;
                int left = (int)floorf(scl); if (left < 0) left = 0;
                int bot = (int)ceilf(scb) + 1; if (bot > F) bot = F;
                int right = (int)ceilf(scr) + 1; if (right > F) right = F;
                g_tl[b][L][p][0] = top;  g_tl[b][L][p][1] = left;
                g_crop[b][L][p][0] = bot - top;  g_crop[b][L][p][1] = right - left;
                if (bot - top > maxh) maxh = bot - top;
                if (right - left > maxw) maxw = right - left;
            }
            g_PH[b][L] = maxh; g_PW[b][L] = maxw;
            for (int s = 0; s < 3; s++) {
                int ph = (int)ceil((double)maxh * scales[s]);
                int pw = (int)ceil((double)maxw * scales[s]);
                if (ph < 1) ph = maxh;
                if (pw < 1) pw = maxw;
                g_PHs[b][L][s] = ph; g_PWs[b][L][s] = pw;
            }
        }
    }
}

// ---------------- weight transpose: [co][ci][k] -> [ci][k][co_pad] ----------
__global__ void wtrans_kernel(const float* __restrict__ wt, float* __restrict__ wbuf,
                              int Cin, int Cout, int Co_pad, int K2, int total) {
    int idx = blockIdx.x * blockDim.x + threadIdx.x;
    if (idx >= total) return;
    int co = idx % Co_pad;
    int t = idx / Co_pad;
    int kk = t % K2;
    int ci = t / K2;
    wbuf[idx] = (co < Cout) ? __ldg(wt + ((size_t)co * Cin + ci) * K2 + kk) : 0.0f;
}

// ---------------- f32x2 tiled conv: 32(x) x 4(y) x 32 couts per block --------
// 256 threads: tx(16) x ty(2) x tc(8). Thread: 2x (packed) * 2y * 4co.
template <int K, int STRIDE, int CS>
__global__ void conv_f2(const float* __restrict__ in, const float* __restrict__ wbuf,
                        const float* __restrict__ bias, float* __restrict__ out,
                        int N, int Cin, int Hin, int Win,
                        int Cout, int Co_pad, int Hout, int Wout,
                        int pad, int relu, int cotiles) {
    constexpr int K2 = K * K;
    constexpr int IH = 3 * STRIDE + K;
    constexpr int IW = 31 * STRIDE + K;

    __shared__ float s_in[CS][IH * IW];
    __shared__ __align__(16) ull s_w[CS][K2][32];   // {w,w} duplicated per cout

    const int tid = threadIdx.x;
    const int tx = tid & 15;
    const int ty = (tid >> 4) & 1;
    const int tc = tid >> 5;

    const int bx = blockIdx.x, by = blockIdx.y;
    const int n   = blockIdx.z / cotiles;
    const int co0 = (blockIdx.z % cotiles) * 32;

    const int ix0 = bx * 32 * STRIDE - pad;
    const int iy0 = by * 4 * STRIDE - pad;

    ull acc[2][4];
#pragma unroll
    for (int yy = 0; yy < 2; yy++)
#pragma unroll
        for (int c = 0; c < 4; c++) acc[yy][c] = 0ULL;

    const size_t in_n = (size_t)n * Cin * Hin * Win;

    for (int ci0 = 0; ci0 < Cin; ci0 += CS) {
        __syncthreads();
        // stage CS input channels
#pragma unroll 2
        for (int i = tid; i < CS * IH * IW; i += 256) {
            int cs = i / (IH * IW);
            int rem = i - cs * (IH * IW);
            int r = rem / IW, c = rem - r * IW;
            int gy = iy0 + r, gx = ix0 + c;
            int ci = ci0 + cs;
            float v = 0.0f;
            if (ci < Cin && (unsigned)gy < (unsigned)Hin && (unsigned)gx < (unsigned)Win)
                v = __ldg(in + in_n + (size_t)ci * Hin * Win + (size_t)gy * Win + gx);
            s_in[cs][rem] = v;
        }
        // stage CS x K2 x 32 duplicated weights
#pragma unroll 2
        for (int i = tid; i < CS * K2 * 32; i += 256) {
            int cs = i / (K2 * 32);
            int rem = i - cs * (K2 * 32);
            int kk = rem >> 5, c = rem & 31;
            int ci = ci0 + cs;
            float w = 0.0f;
            if (ci < Cin)
                w = __ldg(wbuf + (size_t)ci * K2 * Co_pad + (size_t)kk * Co_pad + co0 + c);
            s_w[cs][kk][c] = pack2(w, w);
        }
        __syncthreads();

#pragma unroll
        for (int cs = 0; cs < CS; cs++) {
#pragma unroll
            for (int kh = 0; kh < K; kh++) {
#pragma unroll
                for (int kw = 0; kw < K; kw++) {
                    const ulonglong2* wp =
                        reinterpret_cast<const ulonglong2*>(&s_w[cs][kh * K + kw][tc * 4]);
                    ulonglong2 wa = wp[0];
                    ulonglong2 wb = wp[1];
#pragma unroll
                    for (int yy = 0; yy < 2; yy++) {
                        const float* rp = &s_in[cs][((2 * ty + yy) * STRIDE + kh) * IW
                                                    + 2 * STRIDE * tx + kw];
                        ull iv = pack2(rp[0], rp[STRIDE]);
                        fma2(acc[yy][0], iv, wa.x, acc[yy][0]);
                        fma2(acc[yy][1], iv, wa.y, acc[yy][1]);
                        fma2(acc[yy][2], iv, wb.x, acc[yy][2]);
                        fma2(acc[yy][3], iv, wb.y, acc[yy][3]);
                    }
                }
            }
        }
    }

    const int ox = bx * 32 + 2 * tx;
    if (ox >= Wout) return;
#pragma unroll
    for (int c = 0; c < 4; c++) {
        int co = co0 + tc * 4 + c;
        if (co >= Cout) continue;
        float bv = bias ? __ldg(bias + co) : 0.0f;
#pragma unroll
        for (int yy = 0; yy < 2; yy++) {
            int oy = by * 4 + 2 * ty + yy;
            if (oy >= Hout) continue;
            float2 v = unpack2(acc[yy][c]);
            v.x += bv; v.y += bv;
            if (relu) { v.x = fmaxf(v.x, 0.0f); v.y = fmaxf(v.y, 0.0f); }
            *(float2*)(out + (((size_t)n * Cout + co) * Hout + oy) * Wout + ox) = v;
        }
    }
}

// ---------------- half-pixel bilinear patch extraction ----------------------
__global__ void extract_patches_kernel(const float* __restrict__ fm, float* __restrict__ patches,
                                       int C, int F, int b, int L) {
    int idx = blockIdx.x * blockDim.x + threadIdx.x;
    int total = NP * C * 24 * 24;
    if (idx >= total) return;
    int ox = idx % 24;
    int oy = (idx / 24) % 24;
    int c = (idx / 576) % C;
    int p = idx / (576 * C);
    int PH = g_PH[b][L], PW = g_PW[b][L];
    if (oy >= PH || ox >= PW) return;
    int top = g_tl[b][L][p][0], left = g_tl[b][L][p][1];
    int h = g_crop[b][L][p][0], w = g_crop[b][L][p][1];

    float sy = ((float)oy + 0.5f) * ((float)h / (float)PH) - 0.5f;
    if (sy < 0.0f) sy = 0.0f;
    float sx = ((float)ox + 0.5f) * ((float)w / (float)PW) - 0.5f;
    if (sx < 0.0f) sx = 0.0f;
    int y0 = (int)sy; float ty = sy - (float)y0;
    int x0 = (int)sx; float tx = sx - (float)x0;
    if (y0 > h - 1) { y0 = h - 1; ty = 0.0f; }
    if (x0 > w - 1) { x0 = w - 1; tx = 0.0f; }
    int y1 = min(y0 + 1, h - 1);
    int x1 = min(x0 + 1, w - 1);

    const float* base = fm + ((size_t)c * F + top) * F + left;
    float v00 = base[y0 * F + x0], v01 = base[y0 * F + x1];
    float v10 = base[y1 * F + x0], v11 = base[y1 * F + x1];
    float val = v00 * (1.0f - ty) * (1.0f - tx) + v01 * (1.0f - ty) * tx
              + v10 * ty * (1.0f - tx) + v11 * ty * tx;
    patches[((size_t)(p * C + c) * 24 + oy) * 24 + ox] = val;
}

__global__ void resize_patches_kernel(const float* __restrict__ patches, float* __restrict__ pf,
                                      int C, int b, int L, int s) {
    int idx = blockIdx.x * blockDim.x + threadIdx.x;
    int total = NP * C * 32 * 32;
    if (idx >= total) return;
    int ox = idx % 32;
    int oy = (idx / 32) % 32;
    int c = (idx / 1024) % C;
    int p = idx / (1024 * C);
    int PHs = g_PHs[b][L][s], PWs = g_PWs[b][L][s];
    if (oy >= PHs || ox >= PWs) return;
    int PH = g_PH[b][L], PW = g_PW[b][L];

    float sy = ((float)oy + 0.5f) * ((float)PH / (float)PHs) - 0.5f;
    if (sy < 0.0f) sy = 0.0f;
    float sx = ((float)ox + 0.5f) * ((float)PW / (float)PWs) - 0.5f;
    if (sx < 0.0f) sx = 0.0f;
    int y0 = (int)sy; float ty = sy - (float)y0;
    int x0 = (int)sx; float tx = sx - (float)x0;
    if (y0 > PH - 1) { y0 = PH - 1; ty = 0.0f; }
    if (x0 > PW - 1) { x0 = PW - 1; tx = 0.0f; }
    int y1 = min(y0 + 1, PH - 1);
    int x1 = min(x0 + 1, PW - 1);

    const float* base = patches + (size_t)(p * C + c) * 576;
    float v00 = base[y0 * 24 + x0], v01 = base[y0 * 24 + x1];
    float v10 = base[y1 * 24 + x0], v11 = base[y1 * 24 + x1];
    float val = v00 * (1.0f - ty) * (1.0f - tx) + v01 * (1.0f - ty) * tx
              + v10 * ty * (1.0f - tx) + v11 * ty * tx;
    pf[((size_t)(p * C + c) * 32 + oy) * 32 + ox] = val;
}

// ---------------- correlation: one block per output pixel -------------------
__global__ void sim_kernel(const float* __restrict__ fm, const float* __restrict__ pf,
                           float* __restrict__ simtmp, int C, int F, int b, int L, int s) {
    int blk = blockIdx.x;
    int p = blk / (F * F);
    int rem = blk % (F * F);
    int y = rem / F, x = rem % F;
    int PHs = g_PHs[b][L][s], PWs = g_PWs[b][L][s];
    int padT = PHs >> 1, padL = PWs >> 1;
    int phw = PHs * PWs;
    int tid = threadIdx.x;

    int fmo = -1, pfo = 0;
    if (tid < phw) {
        int i = tid / PWs, j = tid - i * PWs;
        int iy = y + i - padT, ix = x + j - padL;
        if (iy >= 0 && iy < F && ix >= 0 && ix < F) {
            fmo = iy * F + ix;
            pfo = i * 32 + j;
        }
    }
    float a0 = 0.0f, a1 = 0.0f, a2 = 0.0f, a3 = 0.0f;
    if (fmo >= 0) {
        const int FF = F * F;
        const float* fmb = fm + fmo;
        const float* pfb = pf + (size_t)p * C * 1024 + pfo;
        for (int c = 0; c < C; c += 4) {
            a0 = fmaf(__ldg(fmb + (size_t)(c + 0) * FF), __ldg(pfb + ((c + 0) << 10)), a0);
            a1 = fmaf(__ldg(fmb + (size_t)(c + 1) * FF), __ldg(pfb + ((c + 1) << 10)), a1);
            a2 = fmaf(__ldg(fmb + (size_t)(c + 2) * FF), __ldg(pfb + ((c + 2) << 10)), a2);
            a3 = fmaf(__ldg(fmb + (size_t)(c + 3) * FF), __ldg(pfb + ((c + 3) << 10)), a3);
        }
    }
    __shared__ float red[256];
    red[tid] = (a0 + a1) + (a2 + a3);
    __syncthreads();
    for (int off = 128; off > 0; off >>= 1) {
        if (tid < off) red[tid] += red[tid + off];
        __syncthreads();
    }
    if (tid == 0) simtmp[blk] = red[0];
}

__global__ void sim_resize_kernel(const float* __restrict__ simtmp, float* __restrict__ sims,
                                  int F, int b, int ch) {
    int idx = blockIdx.x * blockDim.x + threadIdx.x;
    if (idx >= NP * 48 * 48) return;
    int x = idx % 48;
    int y = (idx / 48) % 48;
    int p = idx / 2304;

    float sy = ((float)y + 0.5f) * ((float)F / 48.0f) - 0.5f;
    if (sy < 0.0f) sy = 0.0f;
    float sx = ((float)x + 0.5f) * ((float)F / 48.0f) - 0.5f;
    if (sx < 0.0f) sx = 0.0f;
    int y0 = (int)sy; float ty = sy - (float)y0;
    int x0 = (int)sx; float tx = sx - (float)x0;
    if (y0 > F - 1) { y0 = F - 1; ty = 0.0f; }
    if (x0 > F - 1) { x0 = F - 1; tx = 0.0f; }
    int y1 = min(y0 + 1, F - 1);
    int x1 = min(x0 + 1, F - 1);

    const float* base = simtmp + (size_t)p * F * F;
    float v00 = base[y0 * F + x0], v01 = base[y0 * F + x1];
    float v10 = base[y1 * F + x0], v11 = base[y1 * F + x1];
    float val = v00 * (1.0f - ty) * (1.0f - tx) + v01 * (1.0f - ty) * tx
              + v10 * ty * (1.0f - tx) + v11 * ty * tx;
    sims[((size_t)(b * NP + p) * 6 + ch) * 2304 + y * 48 + x] = val;
}

// ---------------- align-corners 2x bilinear upsample ------------------------
__global__ void upsample_kernel(const float* __restrict__ in, float* __restrict__ out,
                                int NC, int h, int w) {
    int H = 2 * h, W = 2 * w;
    int idx = blockIdx.x * blockDim.x + threadIdx.x;
    int total = NC * H * W;
    if (idx >= total) return;
    int ox = idx % W;
    int oy = (idx / W) % H;
    int nc = idx / (H * W);

    float stepy = (float)(h - 1) / (float)(H - 1);
    float stepx = (float)(w - 1) / (float)(W - 1);
    float py = (float)oy * stepy;
    float px = (float)ox * stepx;
    int y0 = (int)py; float ty = py - (float)y0;
    int x0 = (int)px; float tx = px - (float)x0;
    if (y0 > h - 1) { y0 = h - 1; ty = 0.0f; }
    if (x0 > w - 1) { x0 = w - 1; tx = 0.0f; }
    int y1 = min(y0 + 1, h - 1);
    int x1 = min(x0 + 1, w - 1);

    const float* ib = in + (size_t)nc * h * w;
    float v00 = ib[y0 * w + x0], v01 = ib[y0 * w + x1];
    float v10 = ib[y1 * w + x0], v11 = ib[y1 * w + x1];
    out[idx] = v00 * (1.0f - ty) * (1.0f - tx) + v01 * (1.0f - ty) * tx
             + v10 * ty * (1.0f - tx) + v11 * ty * tx;
}

// ---------------- fused rw5 (1x1, 32->1) + relu + max over P ----------------
__global__ void tail_kernel(const float* __restrict__ r4, const float* __restrict__ w5,
                            const float* __restrict__ b5, float* __restrict__ out) {
    __shared__ float sw[32];
    if (threadIdx.x < 32) sw[threadIdx.x] = __ldg(w5 + threadIdx.x);
    __syncthreads();
    const int HW = 384 * 384;
    int idx = blockIdx.x * blockDim.x + threadIdx.x;
    if (idx >= NB * HW) return;
    int b = idx / HW;
    int r = idx % HW;
    float bv = __ldg(b5);
    float m = -1e30f;
#pragma unroll
    for (int p = 0; p < NP; p++) {
        const float* base = r4 + ((size_t)(b * NP + p) * 32) * HW + r;
        float s = bv;
#pragma unroll
        for (int c = 0; c < 32; c++)
            s = fmaf(__ldg(base + (size_t)c * HW), sw[c], s);
        s = fmaxf(s, 0.0f);
        m = fmaxf(m, s);
    }
    out[idx] = m;
}

// ---------------- host-side launch helpers ----------------------------------
static inline int cdiv(int a, int b) { return (a + b - 1) / b; }

static float* s_wbuf = nullptr;

static void run_conv(const float* in, const float* w, const float* b, float* out,
                     int N, int Cin, int Hin, int Win, int Cout,
                     int K, int stride, int pad, bool relu) {
    int Hout = (Hin + 2 * pad - K) / stride + 1;
    int Wout = (Win + 2 * pad - K) / stride + 1;
    int cotiles = cdiv(Cout, 32);
    int Co_pad = cotiles * 32;
    int K2 = K * K;

    int wtotal = Cin * K2 * Co_pad;
    wtrans_kernel<<<cdiv(wtotal, 256), 256>>>(w, s_wbuf, Cin, Cout, Co_pad, K2, wtotal);

    dim3 grid(cdiv(Wout, 32), cdiv(Hout, 4), N * cotiles);
    int rl = relu ? 1 : 0;
    if (stride == 2) {
        if (K == 7) conv_f2<7, 2, 1><<<grid, 256>>>(in, s_wbuf, b, out, N, Cin, Hin, Win, Cout, Co_pad, Hout, Wout, pad, rl, cotiles);
        else        conv_f2<3, 2, 2><<<grid, 256>>>(in, s_wbuf, b, out, N, Cin, Hin, Win, Cout, Co_pad, Hout, Wout, pad, rl, cotiles);
    } else {
        if (K == 7)      conv_f2<7, 1, 1><<<grid, 256>>>(in, s_wbuf, b, out, N, Cin, Hin, Win, Cout, Co_pad, Hout, Wout, pad, rl, cotiles);
        else if (K == 5) conv_f2<5, 1, 2><<<grid, 256>>>(in, s_wbuf, b, out, N, Cin, Hin, Win, Cout, Co_pad, Hout, Wout, pad, rl, cotiles);
        else if (K == 3) conv_f2<3, 1, 2><<<grid, 256>>>(in, s_wbuf, b, out, N, Cin, Hin, Win, Cout, Co_pad, Hout, Wout, pad, rl, cotiles);
        else             conv_f2<1, 1, 4><<<grid, 256>>>(in, s_wbuf, b, out, N, Cin, Hin, Win, Cout, Co_pad, Hout, Wout, pad, rl, cotiles);
    }
}

extern "C" void kernel_launch(void* const* d_in, const int* in_sizes, int n_in,
                              void* d_out, int out_size) {
    const float* images = (const float*)d_in[0];
    const float* tlbrs  = (const float*)d_in[1];
    const float* fw1 = (const float*)d_in[2];
    const float* fw2 = (const float*)d_in[3];
    const float* fw3 = (const float*)d_in[4];
    const float* fw4 = (const float*)d_in[5];
    const float* rw1 = (const float*)d_in[6];
    const float* rb1 = (const float*)d_in[7];
    const float* rw2 = (const float*)d_in[8];
    const float* rb2 = (const float*)d_in[9];
    const float* rw3 = (const float*)d_in[10];
    const float* rb3 = (const float*)d_in[11];
    const float* rw4 = (const float*)d_in[12];
    const float* rb4 = (const float*)d_in[13];
    const float* rw5 = (const float*)d_in[14];
    const float* rb5 = (const float*)d_in[15];
    float* out = (float*)d_out;

    float *x1, *x2, *f3, *f4, *patches, *pf, *simtmp, *sims;
    float *r1, *u1, *r2, *u2, *r3, *u3, *r4;
    cudaGetSymbolAddress((void**)&x1, g_x1);
    cudaGetSymbolAddress((void**)&x2, g_x2);
    cudaGetSymbolAddress((void**)&f3, g_f3);
    cudaGetSymbolAddress((void**)&f4, g_f4);
    cudaGetSymbolAddress((void**)&patches, g_patches);
    cudaGetSymbolAddress((void**)&pf, g_pf);
    cudaGetSymbolAddress((void**)&simtmp, g_simtmp);
    cudaGetSymbolAddress((void**)&sims, g_sims);
    cudaGetSymbolAddress((void**)&r1, g_r1);
    cudaGetSymbolAddress((void**)&u1, g_u1);
    cudaGetSymbolAddress((void**)&r2, g_r2);
    cudaGetSymbolAddress((void**)&u2, g_u2);
    cudaGetSymbolAddress((void**)&r3, g_r3);
    cudaGetSymbolAddress((void**)&u3, g_u3);
    cudaGetSymbolAddress((void**)&r4, g_r4);
    cudaGetSymbolAddress((void**)&s_wbuf, g_wbuf);

    // box metadata
    meta_kernel<<<1, 1>>>(tlbrs);

    // backbone
    run_conv(images, fw1, nullptr, x1, 2, 3, 384, 384, 64, 7, 2, 3, true);
    run_conv(x1, fw2, nullptr, x2, 2, 64, 192, 192, 256, 3, 2, 1, true);
    run_conv(x2, fw3, nullptr, f3, 2, 256, 96, 96, 512, 3, 2, 1, true);
    run_conv(f3, fw4, nullptr, f4, 2, 512, 48, 48, 1024, 3, 2, 1, true);

    // similarity features
    for (int b = 0; b < NB; b++) {
        for (int L = 0; L < 2; L++) {
            int C = L ? 1024 : 512;
            int F = L ? 24 : 48;
            const float* fm = L ? (f4 + (size_t)b * 1024 * 24 * 24)
                                : (f3 + (size_t)b * 512 * 48 * 48);
            {
                int total = NP * C * 576;
                extract_patches_kernel<<<cdiv(total, 256), 256>>>(fm, patches, C, F, b, L);
            }
            for (int s = 0; s < 3; s++) {
                int total = NP * C * 1024;
                resize_patches_kernel<<<cdiv(total, 256), 256>>>(patches, pf, C, b, L, s);
                sim_kernel<<<NP * F * F, 256>>>(fm, pf, simtmp, C, F, b, L, s);
                sim_resize_kernel<<<cdiv(NP * 2304, 256), 256>>>(simtmp, sims, F, b, L * 3 + s);
            }
        }
    }

    // regressor
    run_conv(sims, rw1, rb1, r1, 6, 6, 48, 48, 196, 7, 1, 3, true);
    upsample_kernel<<<cdiv(6 * 196 * 96 * 96, 256), 256>>>(r1, u1, 6 * 196, 48, 48);
    run_conv(u1, rw2, rb2, r2, 6, 196, 96, 96, 128, 5, 1, 2, true);
    upsample_kernel<<<cdiv(6 * 128 * 192 * 192, 256), 256>>>(r2, u2, 6 * 128, 96, 96);
    run_conv(u2, rw3, rb3, r3, 6, 128, 192, 192, 64, 3, 1, 1, true);
    upsample_kernel<<<cdiv(6 * 64 * 384 * 384, 256), 256>>>(r3, u3, 6 * 64, 192, 192);
    run_conv(u3, rw4, rb4, r4, 6, 64, 384, 384, 32, 1, 1, 0, true);

    tail_kernel<<<cdiv(NB * 384 * 384, 256), 256>>>(r4, rw5, rb5, out);
}

// round 6
// speedup vs baseline: 1.0424x; 1.0424x over previous
#include <cuda_runtime.h>
#include <math.h>

// ============================================================================
// FamNet pipeline, fp32, register-tiled conv (32 MAC/tap, double-buffered smem).
// ============================================================================

#define NB 2
#define NP 3

// ---------------- device scratch (no allocations allowed) -------------------
__device__ float g_x1[2 * 64 * 192 * 192];
__device__ float g_x2[2 * 256 * 96 * 96];
__device__ float g_f3[2 * 512 * 48 * 48];
__device__ float g_f4[2 * 1024 * 24 * 24];
__device__ float g_patches[3 * 1024 * 24 * 24];   // stride-24 layout
__device__ float g_pf[3 * 1024 * 32 * 32];        // stride-32 layout
__device__ float g_simtmp[3 * 48 * 48];
__device__ float g_sims[2 * 3 * 6 * 48 * 48];
__device__ float g_r1[6 * 196 * 48 * 48];
__device__ float g_u1[6 * 196 * 96 * 96];
__device__ float g_r2[6 * 128 * 96 * 96];
__device__ float g_u2[6 * 128 * 192 * 192];
__device__ float g_r3[6 * 64 * 192 * 192];
__device__ float g_u3[6 * 64 * 384 * 384];
__device__ float g_r4[6 * 32 * 384 * 384];
__device__ float g_wbuf[1024 * 512 * 9];          // transposed weights [ci][k][co_pad]

// ---------------- box / scale metadata (computed on device) -----------------
__device__ int g_tl[2][2][3][2];
__device__ int g_crop[2][2][3][2];
__device__ int g_PH[2][2], g_PW[2][2];
__device__ int g_PHs[2][2][3], g_PWs[2][2][3];

__global__ void meta_kernel(const float* __restrict__ tlbrs) {
    if (threadIdx.x != 0 || blockIdx.x != 0) return;
    const double scales[3] = {1.0, 0.9, 1.1};
    for (int b = 0; b < NB; b++) {
        for (int L = 0; L < 2; L++) {
            int F = (L == 0) ? 48 : 24;
            float inv = (float)F / 384.0f;
            int maxh = 0, maxw = 0;
            for (int p = 0; p < NP; p++) {
                const float* v = tlbrs + (b * NP + p) * 4;
                float sct = v[0] * inv, scl = v[1] * inv;
                float scb = v[2] * inv, scr = v[3] * inv;
                int top = (int)floorf(sct); if (top < 0) top = 0;
                int left = (int)floorf(scl); if (left < 0) left = 0;
                int bot = (int)ceilf(scb) + 1; if (bot > F) bot = F;
                int right = (int)ceilf(scr) + 1; if (right > F) right = F;
                g_tl[b][L][p][0] = top;  g_tl[b][L][p][1] = left;
                g_crop[b][L][p][0] = bot - top;  g_crop[b][L][p][1] = right - left;
                if (bot - top > maxh) maxh = bot - top;
                if (right - left > maxw) maxw = right - left;
            }
            g_PH[b][L] = maxh; g_PW[b][L] = maxw;
            for (int s = 0; s < 3; s++) {
                int ph = (int)ceil((double)maxh * scales[s]);
                int pw = (int)ceil((double)maxw * scales[s]);
                if (ph < 1) ph = maxh;
                if (pw < 1) pw = maxw;
                g_PHs[b][L][s] = ph; g_PWs[b][L][s] = pw;
            }
        }
    }
}

// ---------------- weight transpose: [co][ci][k] -> [ci][k][co_pad] ----------
__global__ void wtrans_kernel(const float* __restrict__ wt, float* __restrict__ wbuf,
                              int Cin, int Cout, int Co_pad, int K2, int total) {
    int idx = blockIdx.x * blockDim.x + threadIdx.x;
    if (idx >= total) return;
    int co = idx % Co_pad;
    int t = idx / Co_pad;
    int kk = t % K2;
    int ci = t / K2;
    wbuf[idx] = (co < Cout) ? __ldg(wt + ((size_t)co * Cin + ci) * K2 + kk) : 0.0f;
}

// ---------------- conv: 32(x) x 4(y) spatial x COB couts per block -----------
// 256 threads: tx(16) x ty(2) x tc(8). Thread: 2x * 2y * (COB/8) couts.
template <int K, int STRIDE, int COB>
__global__ void __launch_bounds__(256)
conv_f3(const float* __restrict__ in, const float* __restrict__ wbuf,
        const float* __restrict__ bias, float* __restrict__ out,
        int N, int Cin, int Hin, int Win,
        int Cout, int Co_pad, int Hout, int Wout,
        int pad, int relu, int cotiles) {
    constexpr int K2 = K * K;
    constexpr int IH = 3 * STRIDE + K;
    constexpr int IW = 31 * STRIDE + K;
    constexpr int CPT = COB / 8;

    __shared__ float s_in[2][IH * IW];
    __shared__ __align__(16) float s_w[2][K2 * COB];

    const int tid = threadIdx.x;
    const int tx = tid & 15;
    const int ty = (tid >> 4) & 1;
    const int tc = tid >> 5;

    const int bx = blockIdx.x, by = blockIdx.y;
    const int n   = blockIdx.z / cotiles;
    const int co0 = (blockIdx.z % cotiles) * COB;

    const int ix0 = bx * 32 * STRIDE - pad;
    const int iy0 = by * 4 * STRIDE - pad;

    float acc[2][2][CPT];
#pragma unroll
    for (int yy = 0; yy < 2; yy++)
#pragma unroll
        for (int xx = 0; xx < 2; xx++)
#pragma unroll
            for (int c = 0; c < CPT; c++) acc[yy][xx][c] = 0.0f;

    const size_t in_n = (size_t)n * Cin * Hin * Win;

    // ---- staging helper (inline) ----
#define STAGE(CI, BUF)                                                          \
    do {                                                                        \
        const float* ip = in + in_n + (size_t)(CI) * Hin * Win;                 \
        for (int i = tid; i < IH * IW; i += 256) {                              \
            int r = i / IW, c = i - r * IW;                                     \
            int gy = iy0 + r, gx = ix0 + c;                                     \
            float v = 0.0f;                                                     \
            if ((unsigned)gy < (unsigned)Hin && (unsigned)gx < (unsigned)Win)   \
                v = __ldg(ip + (size_t)gy * Win + gx);                          \
            s_in[BUF][i] = v;                                                   \
        }                                                                       \
        const float* wp = wbuf + (size_t)(CI) * K2 * Co_pad + co0;              \
        for (int i = tid; i < K2 * COB; i += 256)                               \
            s_w[BUF][i] = __ldg(wp + (i / COB) * Co_pad + (i & (COB - 1)));     \
    } while (0)

    STAGE(0, 0);
    __syncthreads();

    for (int ci = 0; ci < Cin; ci++) {
        const int cur = ci & 1;
        if (ci + 1 < Cin) STAGE(ci + 1, cur ^ 1);

#pragma unroll
        for (int kh = 0; kh < K; kh++) {
#pragma unroll
            for (int kw = 0; kw < K; kw++) {
                float wl[CPT];
                const float* wrow = &s_w[cur][(kh * K + kw) * COB + tc * CPT];
                *(float4*)&wl[0] = *(const float4*)&wrow[0];
                if (CPT == 8) *(float4*)&wl[4] = *(const float4*)&wrow[4];

                float iv[2][2];
#pragma unroll
                for (int yy = 0; yy < 2; yy++)
#pragma unroll
                    for (int xx = 0; xx < 2; xx++)
                        iv[yy][xx] = s_in[cur][((2 * ty + yy) * STRIDE + kh) * IW
                                              + (2 * tx + xx) * STRIDE + kw];
#pragma unroll
                for (int yy = 0; yy < 2; yy++)
#pragma unroll
                    for (int xx = 0; xx < 2; xx++)
#pragma unroll
                        for (int c = 0; c < CPT; c++)
                            acc[yy][xx][c] = fmaf(iv[yy][xx], wl[c], acc[yy][xx][c]);
            }
        }
        __syncthreads();
    }
#undef STAGE

    const int ox = bx * 32 + 2 * tx;
    if (ox >= Wout) return;
#pragma unroll
    for (int c = 0; c < CPT; c++) {
        int co = co0 + tc * CPT + c;
        if (co >= Cout) continue;
        float bv = bias ? __ldg(bias + co) : 0.0f;
#pragma unroll
        for (int yy = 0; yy < 2; yy++) {
            int oy = by * 4 + 2 * ty + yy;
            if (oy >= Hout) continue;
            float v0 = acc[yy][0][c] + bv;
            float v1 = acc[yy][1][c] + bv;
            if (relu) { v0 = fmaxf(v0, 0.0f); v1 = fmaxf(v1, 0.0f); }
            *(float2*)(out + (((size_t)n * Cout + co) * Hout + oy) * Wout + ox)
                = make_float2(v0, v1);
        }
    }
}

// ---------------- half-pixel bilinear patch extraction ----------------------
__global__ void extract_patches_kernel(const float* __restrict__ fm, float* __restrict__ patches,
                                       int C, int F, int b, int L) {
    int idx = blockIdx.x * blockDim.x + threadIdx.x;
    int total = NP * C * 24 * 24;
    if (idx >= total) return;
    int ox = idx % 24;
    int oy = (idx / 24) % 24;
    int c = (idx / 576) % C;
    int p = idx / (576 * C);
    int PH = g_PH[b][L], PW = g_PW[b][L];
    if (oy >= PH || ox >= PW) return;
    int top = g_tl[b][L][p][0], left = g_tl[b][L][p][1];
    int h = g_crop[b][L][p][0], w = g_crop[b][L][p][1];

    float sy = ((float)oy + 0.5f) * ((float)h / (float)PH) - 0.5f;
    if (sy < 0.0f) sy = 0.0f;
    float sx = ((float)ox + 0.5f) * ((float)w / (float)PW) - 0.5f;
    if (sx < 0.0f) sx = 0.0f;
    int y0 = (int)sy; float ty = sy - (float)y0;
    int x0 = (int)sx; float tx = sx - (float)x0;
    if (y0 > h - 1) { y0 = h - 1; ty = 0.0f; }
    if (x0 > w - 1) { x0 = w - 1; tx = 0.0f; }
    int y1 = min(y0 + 1, h - 1);
    int x1 = min(x0 + 1, w - 1);

    const float* base = fm + ((size_t)c * F + top) * F + left;
    float v00 = base[y0 * F + x0], v01 = base[y0 * F + x1];
    float v10 = base[y1 * F + x0], v11 = base[y1 * F + x1];
    float val = v00 * (1.0f - ty) * (1.0f - tx) + v01 * (1.0f - ty) * tx
              + v10 * ty * (1.0f - tx) + v11 * ty * tx;
    patches[((size_t)(p * C + c) * 24 + oy) * 24 + ox] = val;
}

__global__ void resize_patches_kernel(const float* __restrict__ patches, float* __restrict__ pf,
                                      int C, int b, int L, int s) {
    int idx = blockIdx.x * blockDim.x + threadIdx.x;
    int total = NP * C * 32 * 32;
    if (idx >= total) return;
    int ox = idx % 32;
    int oy = (idx / 32) % 32;
    int c = (idx / 1024) % C;
    int p = idx / (1024 * C);
    int PHs = g_PHs[b][L][s], PWs = g_PWs[b][L][s];
    if (oy >= PHs || ox >= PWs) return;
    int PH = g_PH[b][L], PW = g_PW[b][L];

    float sy = ((float)oy + 0.5f) * ((float)PH / (float)PHs) - 0.5f;
    if (sy < 0.0f) sy = 0.0f;
    float sx = ((float)ox + 0.5f) * ((float)PW / (float)PWs) - 0.5f;
    if (sx < 0.0f) sx = 0.0f;
    int y0 = (int)sy; float ty = sy - (float)y0;
    int x0 = (int)sx; float tx = sx - (float)x0;
    if (y0 > PH - 1) { y0 = PH - 1; ty = 0.0f; }
    if (x0 > PW - 1) { x0 = PW - 1; tx = 0.0f; }
    int y1 = min(y0 + 1, PH - 1);
    int x1 = min(x0 + 1, PW - 1);

    const float* base = patches + (size_t)(p * C + c) * 576;
    float v00 = base[y0 * 24 + x0], v01 = base[y0 * 24 + x1];
    float v10 = base[y1 * 24 + x0], v11 = base[y1 * 24 + x1];
    float val = v00 * (1.0f - ty) * (1.0f - tx) + v01 * (1.0f - ty) * tx
              + v10 * ty * (1.0f - tx) + v11 * ty * tx;
    pf[((size_t)(p * C + c) * 32 + oy) * 32 + ox] = val;
}

// ---------------- correlation: one block per output pixel -------------------
__global__ void sim_kernel(const float* __restrict__ fm, const float* __restrict__ pf,
                           float* __restrict__ simtmp, int C, int F, int b, int L, int s) {
    int blk = blockIdx.x;
    int p = blk / (F * F);
    int rem = blk % (F * F);
    int y = rem / F, x = rem % F;
    int PHs = g_PHs[b][L][s], PWs = g_PWs[b][L][s];
    int padT = PHs >> 1, padL = PWs >> 1;
    int phw = PHs * PWs;
    int tid = threadIdx.x;

    int fmo = -1, pfo = 0;
    if (tid < phw) {
        int i = tid / PWs, j = tid - i * PWs;
        int iy = y + i - padT, ix = x + j - padL;
        if (iy >= 0 && iy < F && ix >= 0 && ix < F) {
            fmo = iy * F + ix;
            pfo = i * 32 + j;
        }
    }
    float a0 = 0.0f, a1 = 0.0f, a2 = 0.0f, a3 = 0.0f;
    if (fmo >= 0) {
        const int FF = F * F;
        const float* fmb = fm + fmo;
        const float* pfb = pf + (size_t)p * C * 1024 + pfo;
        for (int c = 0; c < C; c += 4) {
            a0 = fmaf(__ldg(fmb + (size_t)(c + 0) * FF), __ldg(pfb + ((c + 0) << 10)), a0);
            a1 = fmaf(__ldg(fmb + (size_t)(c + 1) * FF), __ldg(pfb + ((c + 1) << 10)), a1);
            a2 = fmaf(__ldg(fmb + (size_t)(c + 2) * FF), __ldg(pfb + ((c + 2) << 10)), a2);
            a3 = fmaf(__ldg(fmb + (size_t)(c + 3) * FF), __ldg(pfb + ((c + 3) << 10)), a3);
        }
    }
    __shared__ float red[256];
    red[tid] = (a0 + a1) + (a2 + a3);
    __syncthreads();
    for (int off = 128; off > 0; off >>= 1) {
        if (tid < off) red[tid] += red[tid + off];
        __syncthreads();
    }
    if (tid == 0) simtmp[blk] = red[0];
}

__global__ void sim_resize_kernel(const float* __restrict__ simtmp, float* __restrict__ sims,
                                  int F, int b, int ch) {
    int idx = blockIdx.x * blockDim.x + threadIdx.x;
    if (idx >= NP * 48 * 48) return;
    int x = idx % 48;
    int y = (idx / 48) % 48;
    int p = idx / 2304;

    float sy = ((float)y + 0.5f) * ((float)F / 48.0f) - 0.5f;
    if (sy < 0.0f) sy = 0.0f;
    float sx = ((float)x + 0.5f) * ((float)F / 48.0f) - 0.5f;
    if (sx < 0.0f) sx = 0.0f;
    int y0 = (int)sy; float ty = sy - (float)y0;
    int x0 = (int)sx; float tx = sx - (float)x0;
    if (y0 > F - 1) { y0 = F - 1; ty = 0.0f; }
    if (x0 > F - 1) { x0 = F - 1; tx = 0.0f; }
    int y1 = min(y0 + 1, F - 1);
    int x1 = min(x0 + 1, F - 1);

    const float* base = simtmp + (size_t)p * F * F;
    float v00 = base[y0 * F + x0], v01 = base[y0 * F + x1];
    float v10 = base[y1 * F + x0], v11 = base[y1 * F + x1];
    float val = v00 * (1.0f - ty) * (1.0f - tx) + v01 * (1.0f - ty) * tx
              + v10 * ty * (1.0f - tx) + v11 * ty * tx;
    sims[((size_t)(b * NP + p) * 6 + ch) * 2304 + y * 48 + x] = val;
}

// ---------------- align-corners 2x bilinear upsample ------------------------
__global__ void upsample_kernel(const float* __restrict__ in, float* __restrict__ out,
                                int NC, int h, int w) {
    int H = 2 * h, W = 2 * w;
    int idx = blockIdx.x * blockDim.x + threadIdx.x;
    int total = NC * H * W;
    if (idx >= total) return;
    int ox = idx % W;
    int oy = (idx / W) % H;
    int nc = idx / (H * W);

    float stepy = (float)(h - 1) / (float)(H - 1);
    float stepx = (float)(w - 1) / (float)(W - 1);
    float py = (float)oy * stepy;
    float px = (float)ox * stepx;
    int y0 = (int)py; float ty = py - (float)y0;
    int x0 = (int)px; float tx = px - (float)x0;
    if (y0 > h - 1) { y0 = h - 1; ty = 0.0f; }
    if (x0 > w - 1) { x0 = w - 1; tx = 0.0f; }
    int y1 = min(y0 + 1, h - 1);
    int x1 = min(x0 + 1, w - 1);

    const float* ib = in + (size_t)nc * h * w;
    float v00 = ib[y0 * w + x0], v01 = ib[y0 * w + x1];
    float v10 = ib[y1 * w + x0], v11 = ib[y1 * w + x1];
    out[idx] = v00 * (1.0f - ty) * (1.0f - tx) + v01 * (1.0f - ty) * tx
             + v10 * ty * (1.0f - tx) + v11 * ty * tx;
}

// ---------------- fused rw5 (1x1, 32->1) + relu + max over P ----------------
__global__ void tail_kernel(const float* __restrict__ r4, const float* __restrict__ w5,
                            const float* __restrict__ b5, float* __restrict__ out) {
    __shared__ float sw[32];
    if (threadIdx.x < 32) sw[threadIdx.x] = __ldg(w5 + threadIdx.x);
    __syncthreads();
    const int HW = 384 * 384;
    int idx = blockIdx.x * blockDim.x + threadIdx.x;
    if (idx >= NB * HW) return;
    int b = idx / HW;
    int r = idx % HW;
    float bv = __ldg(b5);
    float m = -1e30f;
#pragma unroll
    for (int p = 0; p < NP; p++) {
        const float* base = r4 + ((size_t)(b * NP + p) * 32) * HW + r;
        float s = bv;
#pragma unroll
        for (int c = 0; c < 32; c++)
            s = fmaf(__ldg(base + (size_t)c * HW), sw[c], s);
        s = fmaxf(s, 0.0f);
        m = fmaxf(m, s);
    }
    out[idx] = m;
}

// ---------------- host-side launch helpers ----------------------------------
static inline int cdiv(int a, int b) { return (a + b - 1) / b; }

static float* s_wbuf = nullptr;

static void run_conv(const float* in, const float* w, const float* b, float* out,
                     int N, int Cin, int Hin, int Win, int Cout,
                     int K, int stride, int pad, bool relu) {
    int Hout = (Hin + 2 * pad - K) / stride + 1;
    int Wout = (Win + 2 * pad - K) / stride + 1;
    int COB = (Cout >= 64) ? 64 : 32;
    int cotiles = cdiv(Cout, COB);
    int Co_pad = cotiles * COB;
    int K2 = K * K;

    int wtotal = Cin * K2 * Co_pad;
    wtrans_kernel<<<cdiv(wtotal, 256), 256>>>(w, s_wbuf, Cin, Cout, Co_pad, K2, wtotal);

    dim3 grid(cdiv(Wout, 32), cdiv(Hout, 4), N * cotiles);
    int rl = relu ? 1 : 0;
    if (stride == 2) {
        if (K == 7) conv_f3<7, 2, 64><<<grid, 256>>>(in, s_wbuf, b, out, N, Cin, Hin, Win, Cout, Co_pad, Hout, Wout, pad, rl, cotiles);
        else        conv_f3<3, 2, 64><<<grid, 256>>>(in, s_wbuf, b, out, N, Cin, Hin, Win, Cout, Co_pad, Hout, Wout, pad, rl, cotiles);
    } else {
        if (K == 7)      conv_f3<7, 1, 64><<<grid, 256>>>(in, s_wbuf, b, out, N, Cin, Hin, Win, Cout, Co_pad, Hout, Wout, pad, rl, cotiles);
        else if (K == 5) conv_f3<5, 1, 64><<<grid, 256>>>(in, s_wbuf, b, out, N, Cin, Hin, Win, Cout, Co_pad, Hout, Wout, pad, rl, cotiles);
        else if (K == 3) conv_f3<3, 1, 64><<<grid, 256>>>(in, s_wbuf, b, out, N, Cin, Hin, Win, Cout, Co_pad, Hout, Wout, pad, rl, cotiles);
        else             conv_f3<1, 1, 32><<<grid, 256>>>(in, s_wbuf, b, out, N, Cin, Hin, Win, Cout, Co_pad, Hout, Wout, pad, rl, cotiles);
    }
}

extern "C" void kernel_launch(void* const* d_in, const int* in_sizes, int n_in,
                              void* d_out, int out_size) {
    const float* images = (const float*)d_in[0];
    const float* tlbrs  = (const float*)d_in[1];
    const float* fw1 = (const float*)d_in[2];
    const float* fw2 = (const float*)d_in[3];
    const float* fw3 = (const float*)d_in[4];
    const float* fw4 = (const float*)d_in[5];
    const float* rw1 = (const float*)d_in[6];
    const float* rb1 = (const float*)d_in[7];
    const float* rw2 = (const float*)d_in[8];
    const float* rb2 = (const float*)d_in[9];
    const float* rw3 = (const float*)d_in[10];
    const float* rb3 = (const float*)d_in[11];
    const float* rw4 = (const float*)d_in[12];
    const float* rb4 = (const float*)d_in[13];
    const float* rw5 = (const float*)d_in[14];
    const float* rb5 = (const float*)d_in[15];
    float* out = (float*)d_out;

    float *x1, *x2, *f3, *f4, *patches, *pf, *simtmp, *sims;
    float *r1, *u1, *r2, *u2, *r3, *u3, *r4;
    cudaGetSymbolAddress((void**)&x1, g_x1);
    cudaGetSymbolAddress((void**)&x2, g_x2);
    cudaGetSymbolAddress((void**)&f3, g_f3);
    cudaGetSymbolAddress((void**)&f4, g_f4);
    cudaGetSymbolAddress((void**)&patches, g_patches);
    cudaGetSymbolAddress((void**)&pf, g_pf);
    cudaGetSymbolAddress((void**)&simtmp, g_simtmp);
    cudaGetSymbolAddress((void**)&sims, g_sims);
    cudaGetSymbolAddress((void**)&r1, g_r1);
    cudaGetSymbolAddress((void**)&u1, g_u1);
    cudaGetSymbolAddress((void**)&r2, g_r2);
    cudaGetSymbolAddress((void**)&u2, g_u2);
    cudaGetSymbolAddress((void**)&r3, g_r3);
    cudaGetSymbolAddress((void**)&u3, g_u3);
    cudaGetSymbolAddress((void**)&r4, g_r4);
    cudaGetSymbolAddress((void**)&s_wbuf, g_wbuf);

    // box metadata
    meta_kernel<<<1, 1>>>(tlbrs);

    // backbone
    run_conv(images, fw1, nullptr, x1, 2, 3, 384, 384, 64, 7, 2, 3, true);
    run_conv(x1, fw2, nullptr, x2, 2, 64, 192, 192, 256, 3, 2, 1, true);
    run_conv(x2, fw3, nullptr, f3, 2, 256, 96, 96, 512, 3, 2, 1, true);
    run_conv(f3, fw4, nullptr, f4, 2, 512, 48, 48, 1024, 3, 2, 1, true);

    // similarity features
    for (int b = 0; b < NB; b++) {
        for (int L = 0; L < 2; L++) {
            int C = L ? 1024 : 512;
            int F = L ? 24 : 48;
            const float* fm = L ? (f4 + (size_t)b * 1024 * 24 * 24)
                                : (f3 + (size_t)b * 512 * 48 * 48);
            {
                int total = NP * C * 576;
                extract_patches_kernel<<<cdiv(total, 256), 256>>>(fm, patches, C, F, b, L);
            }
            for (int s = 0; s < 3; s++) {
                int total = NP * C * 1024;
                resize_patches_kernel<<<cdiv(total, 256), 256>>>(patches, pf, C, b, L, s);
                sim_kernel<<<NP * F * F, 256>>>(fm, pf, simtmp, C, F, b, L, s);
                sim_resize_kernel<<<cdiv(NP * 2304, 256), 256>>>(simtmp, sims, F, b, L * 3 + s);
            }
        }
    }

    // regressor
    run_conv(sims, rw1, rb1, r1, 6, 6, 48, 48, 196, 7, 1, 3, true);
    upsample_kernel<<<cdiv(6 * 196 * 96 * 96, 256), 256>>>(r1, u1, 6 * 196, 48, 48);
    run_conv(u1, rw2, rb2, r2, 6, 196, 96, 96, 128, 5, 1, 2, true);
    upsample_kernel<<<cdiv(6 * 128 * 192 * 192, 256), 256>>>(r2, u2, 6 * 128, 96, 96);
    run_conv(u2, rw3, rb3, r3, 6, 128, 192, 192, 64, 3, 1, 1, true);
    upsample_kernel<<<cdiv(6 * 64 * 384 * 384, 256), 256>>>(r3, u3, 6 * 64, 192, 192);
    run_conv(u3, rw4, rb4, r4, 6, 64, 384, 384, 32, 1, 1, 0, true);

    tail_kernel<<<cdiv(NB * 384 * 384, 256), 256>>>(r4, rw5, rb5, out);
}

// round 7
// speedup vs baseline: 1.4486x; 1.3897x over previous
#include <cuda_runtime.h>
#include <math.h>

// ============================================================================
// FamNet pipeline, fp32. Round-3 convs + tiled correlation (batched sims).
// ============================================================================

#define NB 2
#define NP 3

// ---------------- device scratch (no allocations allowed) -------------------
__device__ float g_x1[2 * 64 * 192 * 192];
__device__ float g_x2[2 * 256 * 96 * 96];
__device__ float g_f3[2 * 512 * 48 * 48];
__device__ float g_f4[2 * 1024 * 24 * 24];
__device__ float g_patches[2 * 3 * 1024 * 576];        // [b][p][c][24*24]
__device__ float g_pf[2 * 3 * 3 * 1024 * 1024];        // [b][s][p][c][32*32]
__device__ float g_simtmp[2 * 2 * 3 * 3 * 2304];       // [b][L][s][p][F*F]
__device__ float g_sims[2 * 3 * 6 * 48 * 48];
__device__ float g_r1[6 * 196 * 48 * 48];
__device__ float g_u1[6 * 196 * 96 * 96];
__device__ float g_r2[6 * 128 * 96 * 96];
__device__ float g_u2[6 * 128 * 192 * 192];
__device__ float g_r3[6 * 64 * 192 * 192];
__device__ float g_u3[6 * 64 * 384 * 384];
__device__ float g_r4[6 * 32 * 384 * 384];
__device__ float g_wbuf[1024 * 512 * 9];               // [ci][k][co_pad]

// ---------------- box / scale metadata (computed on device) -----------------
__device__ int g_tl[2][2][3][2];
__device__ int g_crop[2][2][3][2];
__device__ int g_PH[2][2], g_PW[2][2];
__device__ int g_PHs[2][2][3], g_PWs[2][2][3];

__global__ void meta_kernel(const float* __restrict__ tlbrs) {
    if (threadIdx.x != 0 || blockIdx.x != 0) return;
    const double scales[3] = {1.0, 0.9, 1.1};
    for (int b = 0; b < NB; b++) {
        for (int L = 0; L < 2; L++) {
            int F = (L == 0) ? 48 : 24;
            float inv = (float)F / 384.0f;
            int maxh = 0, maxw = 0;
            for (int p = 0; p < NP; p++) {
                const float* v = tlbrs + (b * NP + p) * 4;
                float sct = v[0] * inv, scl = v[1] * inv;
                float scb = v[2] * inv, scr = v[3] * inv;
                int top = (int)floorf(sct); if (top < 0) top = 0;
                int left = (int)floorf(scl); if (left < 0) left = 0;
                int bot = (int)ceilf(scb) + 1; if (bot > F) bot = F;
                int right = (int)ceilf(scr) + 1; if (right > F) right = F;
                g_tl[b][L][p][0] = top;  g_tl[b][L][p][1] = left;
                g_crop[b][L][p][0] = bot - top;  g_crop[b][L][p][1] = right - left;
                if (bot - top > maxh) maxh = bot - top;
                if (right - left > maxw) maxw = right - left;
            }
            g_PH[b][L] = maxh; g_PW[b][L] = maxw;
            for (int s = 0; s < 3; s++) {
                int ph = (int)ceil((double)maxh * scales[s]);
                int pw = (int)ceil((double)maxw * scales[s]);
                if (ph < 1) ph = maxh;
                if (pw < 1) pw = maxw;
                g_PHs[b][L][s] = ph; g_PWs[b][L][s] = pw;
            }
        }
    }
}

// ---------------- weight transpose: [co][ci][k] -> [ci][k][co_pad] ----------
__global__ void wtrans_kernel(const float* __restrict__ wt, float* __restrict__ wbuf,
                              int Cin, int Cout, int Co_pad, int K2, int total) {
    int idx = blockIdx.x * blockDim.x + threadIdx.x;
    if (idx >= total) return;
    int co = idx % Co_pad;
    int t = idx / Co_pad;
    int kk = t % K2;
    int ci = t / K2;
    wbuf[idx] = (co < Cout) ? __ldg(wt + ((size_t)co * Cin + ci) * K2 + kk) : 0.0f;
}

// ---------------- conv (round-3): 32x4 spatial x 32 couts per block ----------
template <int K, int STRIDE>
__global__ void conv_tiled2(const float* __restrict__ in, const float* __restrict__ wbuf,
                            const float* __restrict__ bias, float* __restrict__ out,
                            int N, int Cin, int Hin, int Win,
                            int Cout, int Co_pad, int Hout, int Wout,
                            int pad, int relu, int cotiles) {
    constexpr int K2 = K * K;
    constexpr int IH = 3 * STRIDE + K;
    constexpr int IW = 31 * STRIDE + K;

    __shared__ float s_in[IH * IW];
    __shared__ float4 s_w[K2 * 8];

    const int tid = threadIdx.x;
    const int tx = tid & 15;
    const int ty = (tid >> 4) & 1;
    const int tc = tid >> 5;

    const int bx = blockIdx.x, by = blockIdx.y;
    const int n   = blockIdx.z / cotiles;
    const int co0 = (blockIdx.z % cotiles) * 32;

    const int ix0 = bx * 32 * STRIDE - pad;
    const int iy0 = by * 4 * STRIDE - pad;

    float acc[2][2][4] = {};
    const size_t in_n = (size_t)n * Cin * Hin * Win;

    for (int ci = 0; ci < Cin; ci++) {
        __syncthreads();
        const float* ip = in + in_n + (size_t)ci * Hin * Win;
#pragma unroll 2
        for (int i = tid; i < IH * IW; i += 256) {
            int r = i / IW, c = i - r * IW;
            int gy = iy0 + r, gx = ix0 + c;
            float v = 0.0f;
            if ((unsigned)gy < (unsigned)Hin && (unsigned)gx < (unsigned)Win)
                v = __ldg(ip + (size_t)gy * Win + gx);
            s_in[i] = v;
        }
        const float* wp = wbuf + (size_t)ci * K2 * Co_pad + co0;
#pragma unroll 2
        for (int i = tid; i < K2 * 32; i += 256) {
            int kk = i >> 5, c = i & 31;
            ((float*)s_w)[i] = __ldg(wp + kk * Co_pad + c);
        }
        __syncthreads();

#pragma unroll
        for (int kh = 0; kh < K; kh++) {
#pragma unroll
            for (int kw = 0; kw < K; kw++) {
                float4 w = s_w[(kh * K + kw) * 8 + tc];
                float iv[2][2];
#pragma unroll
                for (int yy = 0; yy < 2; yy++)
#pragma unroll
                    for (int xx = 0; xx < 2; xx++)
                        iv[yy][xx] = s_in[((2 * ty + yy) * STRIDE + kh) * IW
                                          + (2 * tx + xx) * STRIDE + kw];
#pragma unroll
                for (int yy = 0; yy < 2; yy++)
#pragma unroll
                    for (int xx = 0; xx < 2; xx++) {
                        acc[yy][xx][0] = fmaf(iv[yy][xx], w.x, acc[yy][xx][0]);
                        acc[yy][xx][1] = fmaf(iv[yy][xx], w.y, acc[yy][xx][1]);
                        acc[yy][xx][2] = fmaf(iv[yy][xx], w.z, acc[yy][xx][2]);
                        acc[yy][xx][3] = fmaf(iv[yy][xx], w.w, acc[yy][xx][3]);
                    }
            }
        }
    }

    const int ox = bx * 32 + 2 * tx;
    if (ox >= Wout) return;
#pragma unroll
    for (int c = 0; c < 4; c++) {
        int co = co0 + tc * 4 + c;
        if (co >= Cout) continue;
        float bv = bias ? __ldg(bias + co) : 0.0f;
#pragma unroll
        for (int yy = 0; yy < 2; yy++) {
            int oy = by * 4 + 2 * ty + yy;
            if (oy >= Hout) continue;
            float v0 = acc[yy][0][c] + bv;
            float v1 = acc[yy][1][c] + bv;
            if (relu) { v0 = fmaxf(v0, 0.0f); v1 = fmaxf(v1, 0.0f); }
            *(float2*)(out + (((size_t)n * Cout + co) * Hout + oy) * Wout + ox)
                = make_float2(v0, v1);
        }
    }
}

// ---------------- patch extraction for both b, one L -------------------------
__global__ void extract_patches_all(const float* __restrict__ fmbase, float* __restrict__ patches,
                                    int C, int F, int L) {
    int idx = blockIdx.x * blockDim.x + threadIdx.x;
    int total = NB * NP * C * 576;
    if (idx >= total) return;
    int ox = idx % 24;
    int oy = (idx / 24) % 24;
    int c = (idx / 576) % C;
    int p = (idx / (576 * C)) % NP;
    int b = idx / (576 * C * NP);
    int PH = g_PH[b][L], PW = g_PW[b][L];
    if (oy >= PH || ox >= PW) return;
    int top = g_tl[b][L][p][0], left = g_tl[b][L][p][1];
    int h = g_crop[b][L][p][0], w = g_crop[b][L][p][1];

    float sy = ((float)oy + 0.5f) * ((float)h / (float)PH) - 0.5f;
    if (sy < 0.0f) sy = 0.0f;
    float sx = ((float)ox + 0.5f) * ((float)w / (float)PW) - 0.5f;
    if (sx < 0.0f) sx = 0.0f;
    int y0 = (int)sy; float ty = sy - (float)y0;
    int x0 = (int)sx; float tx = sx - (float)x0;
    if (y0 > h - 1) { y0 = h - 1; ty = 0.0f; }
    if (x0 > w - 1) { x0 = w - 1; tx = 0.0f; }
    int y1 = min(y0 + 1, h - 1);
    int x1 = min(x0 + 1, w - 1);

    const float* base = fmbase + (size_t)b * C * F * F + ((size_t)c * F + top) * F + left;
    float v00 = base[y0 * F + x0], v01 = base[y0 * F + x1];
    float v10 = base[y1 * F + x0], v11 = base[y1 * F + x1];
    float val = v00 * (1.0f - ty) * (1.0f - tx) + v01 * (1.0f - ty) * tx
              + v10 * ty * (1.0f - tx) + v11 * ty * tx;
    patches[((size_t)((b * NP + p) * C + c)) * 576 + oy * 24 + ox] = val;
}

// ---------------- resize patches -> pf for all (b,s,p,c), one L -------------
__global__ void resize_pf_all(const float* __restrict__ patches, float* __restrict__ pf,
                              int C, int L) {
    int idx = blockIdx.x * blockDim.x + threadIdx.x;
    int total = NB * 3 * NP * C * 1024;
    if (idx >= total) return;
    int ox = idx & 31;
    int oy = (idx >> 5) & 31;
    int c = (idx >> 10) % C;
    int rest = idx / (1024 * C);
    int p = rest % NP;
    int s = (rest / NP) % 3;
    int b = rest / (NP * 3);

    int PHs = g_PHs[b][L][s], PWs = g_PWs[b][L][s];
    if (oy >= PHs || ox >= PWs) return;
    int PH = g_PH[b][L], PW = g_PW[b][L];

    float sy = ((float)oy + 0.5f) * ((float)PH / (float)PHs) - 0.5f;
    if (sy < 0.0f) sy = 0.0f;
    float sx = ((float)ox + 0.5f) * ((float)PW / (float)PWs) - 0.5f;
    if (sx < 0.0f) sx = 0.0f;
    int y0 = (int)sy; float ty = sy - (float)y0;
    int x0 = (int)sx; float tx = sx - (float)x0;
    if (y0 > PH - 1) { y0 = PH - 1; ty = 0.0f; }
    if (x0 > PW - 1) { x0 = PW - 1; tx = 0.0f; }
    int y1 = min(y0 + 1, PH - 1);
    int x1 = min(x0 + 1, PW - 1);

    const float* base = patches + ((size_t)((b * NP + p) * C + c)) * 576;
    float v00 = base[y0 * 24 + x0], v01 = base[y0 * 24 + x1];
    float v10 = base[y1 * 24 + x0], v11 = base[y1 * 24 + x1];
    float val = v00 * (1.0f - ty) * (1.0f - tx) + v01 * (1.0f - ty) * tx
              + v10 * ty * (1.0f - tx) + v11 * ty * tx;
    pf[((size_t)(((b * 3 + s) * NP + p) * C + c) << 10) + oy * 32 + ox] = val;
}

// ---------------- zero accumulator ------------------------------------------
__global__ void zero_kernel(float* __restrict__ buf, int n) {
    int idx = blockIdx.x * blockDim.x + threadIdx.x;
    if (idx < n) buf[idx] = 0.0f;
}

// ---------------- tiled correlation ------------------------------------------
// One block = full FxF output for (b,s) over one channel chunk; 3 p together.
// 256 threads = 16x16; thread computes 3x3 pixels x 3 p = 27 accumulators.
__global__ void __launch_bounds__(256)
sim_tiled(const float* __restrict__ fmbase, const float* __restrict__ pf,
          float* __restrict__ simtmp, int C, int F, int L, int nchunks, int cpc) {
    __shared__ float s_fm[63 * 64];
    __shared__ float s_pf[3][16 * 32];

    const int tid = threadIdx.x;
    const int tx = tid & 15, ty = tid >> 4;

    int chunk = blockIdx.x % nchunks;
    int bs = blockIdx.x / nchunks;     // b*3+s
    int b = bs / 3, s = bs % 3;

    int PHs = g_PHs[b][L][s], PWs = g_PWs[b][L][s];
    int padT = PHs >> 1, padL = PWs >> 1;

    const int FF = F * F;
    const float* fm = fmbase + (size_t)b * C * FF;
    const float* pfb = pf + ((size_t)(bs * NP) * C << 10);
    int c0 = chunk * cpc;

    float acc[3][3][3];   // [p][ry][rx]
#pragma unroll
    for (int p = 0; p < 3; p++)
#pragma unroll
        for (int ry = 0; ry < 3; ry++)
#pragma unroll
            for (int rx = 0; rx < 3; rx++) acc[p][ry][rx] = 0.0f;

    const int iy0 = -padT, ix0 = -padL;
    const int pfrows = PHs * 32;

    for (int c = c0; c < c0 + cpc; c++) {
        __syncthreads();
        // stage fm channel patch (63x64, zero-padded)
        const float* fmc = fm + (size_t)c * FF;
        for (int i = tid; i < 63 * 64; i += 256) {
            int r = i >> 6, cc = i & 63;
            int gy = iy0 + r, gx = ix0 + cc;
            float v = 0.0f;
            if ((unsigned)gy < (unsigned)F && (unsigned)gx < (unsigned)F)
                v = __ldg(fmc + gy * F + gx);
            s_fm[i] = v;
        }
        // stage pf rows for the 3 patches
        for (int i = tid; i < 3 * pfrows; i += 256) {
            int p = i / pfrows;
            int rem = i - p * pfrows;
            s_pf[p][rem] = __ldg(pfb + (((size_t)(p * C + c)) << 10) + rem);
        }
        __syncthreads();

        for (int i = 0; i < PHs; i++) {
            const float* fr = &s_fm[(ty + i) * 64 + tx];
            const float* p0 = &s_pf[0][i * 32];
            const float* p1 = &s_pf[1][i * 32];
            const float* p2 = &s_pf[2][i * 32];
            for (int j = 0; j < PWs; j++) {
                float w0 = p0[j], w1 = p1[j], w2 = p2[j];
                float v[3][3];
#pragma unroll
                for (int ry = 0; ry < 3; ry++)
#pragma unroll
                    for (int rx = 0; rx < 3; rx++)
                        v[ry][rx] = fr[(ry * 16) * 64 + rx * 16 + j];
#pragma unroll
                for (int ry = 0; ry < 3; ry++)
#pragma unroll
                    for (int rx = 0; rx < 3; rx++) {
                        acc[0][ry][rx] = fmaf(v[ry][rx], w0, acc[0][ry][rx]);
                        acc[1][ry][rx] = fmaf(v[ry][rx], w1, acc[1][ry][rx]);
                        acc[2][ry][rx] = fmaf(v[ry][rx], w2, acc[2][ry][rx]);
                    }
            }
        }
    }

    // accumulate into simtmp[b][L][s][p][y*F+x]
#pragma unroll
    for (int p = 0; p < 3; p++) {
        float* dst = simtmp + (size_t)(((b * 2 + L) * 3 + s) * NP + p) * 2304;
#pragma unroll
        for (int ry = 0; ry < 3; ry++) {
            int y = ty + ry * 16;
            if (y >= F) continue;
#pragma unroll
            for (int rx = 0; rx < 3; rx++) {
                int x = tx + rx * 16;
                if (x >= F) continue;
                atomicAdd(dst + y * F + x, acc[p][ry][rx]);
            }
        }
    }
}

// ---------------- resize all sims to 48x48 -----------------------------------
__global__ void sim_resize_all(const float* __restrict__ simtmp, float* __restrict__ sims) {
    int idx = blockIdx.x * blockDim.x + threadIdx.x;
    int total = NB * 2 * 3 * NP * 2304;
    if (idx >= total) return;
    int x = idx % 48;
    int y = (idx / 48) % 48;
    int p = (idx / 2304) % NP;
    int s = (idx / (2304 * NP)) % 3;
    int L = (idx / (2304 * NP * 3)) % 2;
    int b = idx / (2304 * NP * 3 * 2);
    int F = L ? 24 : 48;

    float sy = ((float)y + 0.5f) * ((float)F / 48.0f) - 0.5f;
    if (sy < 0.0f) sy = 0.0f;
    float sx = ((float)x + 0.5f) * ((float)F / 48.0f) - 0.5f;
    if (sx < 0.0f) sx = 0.0f;
    int y0 = (int)sy; float ty = sy - (float)y0;
    int x0 = (int)sx; float tx = sx - (float)x0;
    if (y0 > F - 1) { y0 = F - 1; ty = 0.0f; }
    if (x0 > F - 1) { x0 = F - 1; tx = 0.0f; }
    int y1 = min(y0 + 1, F - 1);
    int x1 = min(x0 + 1, F - 1);

    const float* base = simtmp + (size_t)(((b * 2 + L) * 3 + s) * NP + p) * 2304;
    float v00 = base[y0 * F + x0], v01 = base[y0 * F + x1];
    float v10 = base[y1 * F + x0], v11 = base[y1 * F + x1];
    float val = v00 * (1.0f - ty) * (1.0f - tx) + v01 * (1.0f - ty) * tx
              + v10 * ty * (1.0f - tx) + v11 * ty * tx;
    int ch = L * 3 + s;
    sims[((size_t)(b * NP + p) * 6 + ch) * 2304 + y * 48 + x] = val;
}

// ---------------- align-corners 2x bilinear upsample ------------------------
__global__ void upsample_kernel(const float* __restrict__ in, float* __restrict__ out,
                                int NC, int h, int w) {
    int H = 2 * h, W = 2 * w;
    int idx = blockIdx.x * blockDim.x + threadIdx.x;
    int total = NC * H * W;
    if (idx >= total) return;
    int ox = idx % W;
    int oy = (idx / W) % H;
    int nc = idx / (H * W);

    float stepy = (float)(h - 1) / (float)(H - 1);
    float stepx = (float)(w - 1) / (float)(W - 1);
    float py = (float)oy * stepy;
    float px = (float)ox * stepx;
    int y0 = (int)py; float ty = py - (float)y0;
    int x0 = (int)px; float tx = px - (float)x0;
    if (y0 > h - 1) { y0 = h - 1; ty = 0.0f; }
    if (x0 > w - 1) { x0 = w - 1; tx = 0.0f; }
    int y1 = min(y0 + 1, h - 1);
    int x1 = min(x0 + 1, w - 1);

    const float* ib = in + (size_t)nc * h * w;
    float v00 = ib[y0 * w + x0], v01 = ib[y0 * w + x1];
    float v10 = ib[y1 * w + x0], v11 = ib[y1 * w + x1];
    out[idx] = v00 * (1.0f - ty) * (1.0f - tx) + v01 * (1.0f - ty) * tx
             + v10 * ty * (1.0f - tx) + v11 * ty * tx;
}

// ---------------- fused rw5 (1x1, 32->1) + relu + max over P ----------------
__global__ void tail_kernel(const float* __restrict__ r4, const float* __restrict__ w5,
                            const float* __restrict__ b5, float* __restrict__ out) {
    __shared__ float sw[32];
    if (threadIdx.x < 32) sw[threadIdx.x] = __ldg(w5 + threadIdx.x);
    __syncthreads();
    const int HW = 384 * 384;
    int idx = blockIdx.x * blockDim.x + threadIdx.x;
    if (idx >= NB * HW) return;
    int b = idx / HW;
    int r = idx % HW;
    float bv = __ldg(b5);
    float m = -1e30f;
#pragma unroll
    for (int p = 0; p < NP; p++) {
        const float* base = r4 + ((size_t)(b * NP + p) * 32) * HW + r;
        float s = bv;
#pragma unroll
        for (int c = 0; c < 32; c++)
            s = fmaf(__ldg(base + (size_t)c * HW), sw[c], s);
        s = fmaxf(s, 0.0f);
        m = fmaxf(m, s);
    }
    out[idx] = m;
}

// ---------------- host-side launch helpers ----------------------------------
static inline int cdiv(int a, int b) { return (a + b - 1) / b; }

static float* s_wbuf = nullptr;

static void run_conv(const float* in, const float* w, const float* b, float* out,
                     int N, int Cin, int Hin, int Win, int Cout,
                     int K, int stride, int pad, bool relu) {
    int Hout = (Hin + 2 * pad - K) / stride + 1;
    int Wout = (Win + 2 * pad - K) / stride + 1;
    int cotiles = cdiv(Cout, 32);
    int Co_pad = cotiles * 32;
    int K2 = K * K;

    int wtotal = Cin * K2 * Co_pad;
    wtrans_kernel<<<cdiv(wtotal, 256), 256>>>(w, s_wbuf, Cin, Cout, Co_pad, K2, wtotal);

    dim3 grid(cdiv(Wout, 32), cdiv(Hout, 4), N * cotiles);
    int rl = relu ? 1 : 0;
    if (stride == 2) {
        if (K == 7) conv_tiled2<7, 2><<<grid, 256>>>(in, s_wbuf, b, out, N, Cin, Hin, Win, Cout, Co_pad, Hout, Wout, pad, rl, cotiles);
        else        conv_tiled2<3, 2><<<grid, 256>>>(in, s_wbuf, b, out, N, Cin, Hin, Win, Cout, Co_pad, Hout, Wout, pad, rl, cotiles);
    } else {
        if (K == 7)      conv_tiled2<7, 1><<<grid, 256>>>(in, s_wbuf, b, out, N, Cin, Hin, Win, Cout, Co_pad, Hout, Wout, pad, rl, cotiles);
        else if (K == 5) conv_tiled2<5, 1><<<grid, 256>>>(in, s_wbuf, b, out, N, Cin, Hin, Win, Cout, Co_pad, Hout, Wout, pad, rl, cotiles);
        else if (K == 3) conv_tiled2<3, 1><<<grid, 256>>>(in, s_wbuf, b, out, N, Cin, Hin, Win, Cout, Co_pad, Hout, Wout, pad, rl, cotiles);
        else             conv_tiled2<1, 1><<<grid, 256>>>(in, s_wbuf, b, out, N, Cin, Hin, Win, Cout, Co_pad, Hout, Wout, pad, rl, cotiles);
    }
}

extern "C" void kernel_launch(void* const* d_in, const int* in_sizes, int n_in,
                              void* d_out, int out_size) {
    const float* images = (const float*)d_in[0];
    const float* tlbrs  = (const float*)d_in[1];
    const float* fw1 = (const float*)d_in[2];
    const float* fw2 = (const float*)d_in[3];
    const float* fw3 = (const float*)d_in[4];
    const float* fw4 = (const float*)d_in[5];
    const float* rw1 = (const float*)d_in[6];
    const float* rb1 = (const float*)d_in[7];
    const float* rw2 = (const float*)d_in[8];
    const float* rb2 = (const float*)d_in[9];
    const float* rw3 = (const float*)d_in[10];
    const float* rb3 = (const float*)d_in[11];
    const float* rw4 = (const float*)d_in[12];
    const float* rb4 = (const float*)d_in[13];
    const float* rw5 = (const float*)d_in[14];
    const float* rb5 = (const float*)d_in[15];
    float* out = (float*)d_out;

    float *x1, *x2, *f3, *f4, *patches, *pf, *simtmp, *sims;
    float *r1, *u1, *r2, *u2, *r3, *u3, *r4;
    cudaGetSymbolAddress((void**)&x1, g_x1);
    cudaGetSymbolAddress((void**)&x2, g_x2);
    cudaGetSymbolAddress((void**)&f3, g_f3);
    cudaGetSymbolAddress((void**)&f4, g_f4);
    cudaGetSymbolAddress((void**)&patches, g_patches);
    cudaGetSymbolAddress((void**)&pf, g_pf);
    cudaGetSymbolAddress((void**)&simtmp, g_simtmp);
    cudaGetSymbolAddress((void**)&sims, g_sims);
    cudaGetSymbolAddress((void**)&r1, g_r1);
    cudaGetSymbolAddress((void**)&u1, g_u1);
    cudaGetSymbolAddress((void**)&r2, g_r2);
    cudaGetSymbolAddress((void**)&u2, g_u2);
    cudaGetSymbolAddress((void**)&r3, g_r3);
    cudaGetSymbolAddress((void**)&u3, g_u3);
    cudaGetSymbolAddress((void**)&r4, g_r4);
    cudaGetSymbolAddress((void**)&s_wbuf, g_wbuf);

    // box metadata
    meta_kernel<<<1, 1>>>(tlbrs);

    // backbone
    run_conv(images, fw1, nullptr, x1, 2, 3, 384, 384, 64, 7, 2, 3, true);
    run_conv(x1, fw2, nullptr, x2, 2, 64, 192, 192, 256, 3, 2, 1, true);
    run_conv(x2, fw3, nullptr, f3, 2, 256, 96, 96, 512, 3, 2, 1, true);
    run_conv(f3, fw4, nullptr, f4, 2, 512, 48, 48, 1024, 3, 2, 1, true);

    // similarity features (batched)
    const int SIMTMP_N = 2 * 2 * 3 * 3 * 2304;
    zero_kernel<<<cdiv(SIMTMP_N, 256), 256>>>(simtmp, SIMTMP_N);

    // L = 0 (f3: C=512, F=48)
    {
        int C = 512, F = 48, L = 0;
        int te = NB * NP * C * 576;
        extract_patches_all<<<cdiv(te, 256), 256>>>(f3, patches, C, F, L);
        int tr = NB * 3 * NP * C * 1024;
        resize_pf_all<<<cdiv(tr, 256), 256>>>(patches, pf, C, L);
        int nchunks = 32, cpc = C / 32;           // 192 blocks, 16 ch each
        sim_tiled<<<6 * nchunks, 256>>>(f3, pf, simtmp, C, F, L, nchunks, cpc);
    }
    // L = 1 (f4: C=1024, F=24)
    {
        int C = 1024, F = 24, L = 1;
        int te = NB * NP * C * 576;
        extract_patches_all<<<cdiv(te, 256), 256>>>(f4, patches, C, F, L);
        int tr = NB * 3 * NP * C * 1024;
        resize_pf_all<<<cdiv(tr, 256), 256>>>(patches, pf, C, L);
        int nchunks = 32, cpc = C / 32;           // 192 blocks, 32 ch each
        sim_tiled<<<6 * nchunks, 256>>>(f4, pf, simtmp, C, F, L, nchunks, cpc);
    }
    {
        int ts = NB * 2 * 3 * NP * 2304;
        sim_resize_all<<<cdiv(ts, 256), 256>>>(simtmp, sims);
    }

    // regressor
    run_conv(sims, rw1, rb1, r1, 6, 6, 48, 48, 196, 7, 1, 3, true);
    upsample_kernel<<<cdiv(6 * 196 * 96 * 96, 256), 256>>>(r1, u1, 6 * 196, 48, 48);
    run_conv(u1, rw2, rb2, r2, 6, 196, 96, 96, 128, 5, 1, 2, true);
    upsample_kernel<<<cdiv(6 * 128 * 192 * 192, 256), 256>>>(r2, u2, 6 * 128, 96, 96);
    run_conv(u2, rw3, rb3, r3, 6, 128, 192, 192, 64, 3, 1, 1, true);
    upsample_kernel<<<cdiv(6 * 64 * 384 * 384, 256), 256>>>(r3, u3, 6 * 64, 192, 192);
    run_conv(u3, rw4, rb4, r4, 6, 64, 384, 384, 32, 1, 1, 0, true);

    tail_kernel<<<cdiv(NB * 384 * 384, 256), 256>>>(r4, rw5, rb5, out);
}

// round 8
// speedup vs baseline: 1.9472x; 1.3442x over previous
#include <cuda_runtime.h>
#include <cuda_bf16.h>
#include <math.h>

// ============================================================================
// FamNet pipeline. bf16 split-precision mma.sync convs + tiled correlation.
// ============================================================================

#define NB 2
#define NP 3

// ---------------- device scratch (no allocations allowed) -------------------
__device__ float g_x1[2 * 64 * 192 * 192];
__device__ float g_x2[2 * 256 * 96 * 96];
__device__ float g_f3[2 * 512 * 48 * 48];
__device__ float g_f4[2 * 1024 * 24 * 24];
__device__ float g_patches[2 * 3 * 1024 * 576];
__device__ float g_pf[2 * 3 * 3 * 1024 * 1024];
__device__ float g_simtmp[2 * 2 * 3 * 3 * 2304];
__device__ float g_sims[2 * 3 * 6 * 48 * 48];
__device__ float g_r1[6 * 196 * 48 * 48];
__device__ float g_u1[6 * 196 * 96 * 96];
__device__ float g_r2[6 * 128 * 96 * 96];
__device__ float g_u2[6 * 128 * 192 * 192];
__device__ float g_r3[6 * 64 * 192 * 192];
__device__ float g_u3[6 * 64 * 384 * 384];
__device__ float g_r4[6 * 32 * 384 * 384];
__device__ float g_wbuf[512 * 49 * 224];              // scalar-path weights [ci][k][co_pad]
__device__ uint4 g_wq[1200000];                       // mma-path weights

// ---------------- box / scale metadata --------------------------------------
__device__ int g_tl[2][2][3][2];
__device__ int g_crop[2][2][3][2];
__device__ int g_PH[2][2], g_PW[2][2];
__device__ int g_PHs[2][2][3], g_PWs[2][2][3];

__global__ void meta_kernel(const float* __restrict__ tlbrs) {
    if (threadIdx.x != 0 || blockIdx.x != 0) return;
    const double scales[3] = {1.0, 0.9, 1.1};
    for (int b = 0; b < NB; b++) {
        for (int L = 0; L < 2; L++) {
            int F = (L == 0) ? 48 : 24;
            float inv = (float)F / 384.0f;
            int maxh = 0, maxw = 0;
            for (int p = 0; p < NP; p++) {
                const float* v = tlbrs + (b * NP + p) * 4;
                float sct = v[0] * inv, scl = v[1] * inv;
                float scb = v[2] * inv, scr = v[3] * inv;
                int top = (int)floorf(sct); if (top < 0) top = 0;
                int left = (int)floorf(scl); if (left < 0) left = 0;
                int bot = (int)ceilf(scb) + 1; if (bot > F) bot = F;
                int right = (int)ceilf(scr) + 1; if (right > F) right = F;
                g_tl[b][L][p][0] = top;  g_tl[b][L][p][1] = left;
                g_crop[b][L][p][0] = bot - top;  g_crop[b][L][p][1] = right - left;
                if (bot - top > maxh) maxh = bot - top;
                if (right - left > maxw) maxw = right - left;
            }
            g_PH[b][L] = maxh; g_PW[b][L] = maxw;
            for (int s = 0; s < 3; s++) {
                int ph = (int)ceil((double)maxh * scales[s]);
                int pw = (int)ceil((double)maxw * scales[s]);
                if (ph < 1) ph = maxh;
                if (pw < 1) pw = maxw;
                g_PHs[b][L][s] = ph; g_PWs[b][L][s] = pw;
            }
        }
    }
}

// ---------------- helpers ----------------------------------------------------
__device__ __forceinline__ unsigned pk(float a, float b) {
    unsigned ha = (unsigned)__bfloat16_as_ushort(__float2bfloat16_rn(a));
    unsigned hb = (unsigned)__bfloat16_as_ushort(__float2bfloat16_rn(b));
    return ha | (hb << 16);
}
__device__ __forceinline__ float bhi(float v) {
    return __bfloat162float(__float2bfloat16_rn(v));
}

#define MMA(d, a, bb0, bb1)                                                       \
    asm volatile("mma.sync.aligned.m16n8k16.row.col.f32.bf16.bf16.f32 "           \
                 "{%0,%1,%2,%3},{%4,%5,%6,%7},{%8,%9},{%0,%1,%2,%3};"             \
                 : "+f"(d[0]), "+f"(d[1]), "+f"(d[2]), "+f"(d[3])                 \
                 : "r"(a[0]), "r"(a[1]), "r"(a[2]), "r"(a[3]), "r"(bb0), "r"(bb1))

// ---------------- mma weight transform ---------------------------------------
// wq[t][nt][lane] = uint4{ b0hi, b1hi, b0lo, b1lo } for mma B fragments.
__global__ void wq_kernel(const float* __restrict__ wt, uint4* __restrict__ wq,
                          int Cin, int Cout, int K2, int ntiles, int total) {
    int idx = blockIdx.x * blockDim.x + threadIdx.x;
    if (idx >= total) return;
    int lane = idx & 31;
    int nt = (idx >> 5) % ntiles;
    int t = idx / (32 * ntiles);
    int n = nt * 8 + (lane >> 2);
    int k0 = t * 16 + (lane & 3) * 2;

    float w[4], whi[4], wlo[4];
#pragma unroll
    for (int j = 0; j < 4; j++) {
        int k = k0 + (j >> 1) * 8 + (j & 1);
        int ci = k / K2, kk = k - ci * K2;
        w[j] = (ci < Cin && n < Cout) ? __ldg(wt + ((size_t)n * Cin + ci) * K2 + kk) : 0.0f;
        whi[j] = bhi(w[j]);
        wlo[j] = w[j] - whi[j];
    }
    uint4 o;
    o.x = pk(whi[0], whi[1]);
    o.y = pk(whi[2], whi[3]);
    o.z = pk(wlo[0], wlo[1]);
    o.w = pk(wlo[2], wlo[3]);
    wq[idx] = o;
}

// ---------------- mma conv: 32x4 px x 32 couts, bf16 3-product split ---------
template <int K, int STRIDE>
__global__ void __launch_bounds__(256)
conv_mma(const float* __restrict__ in, const uint4* __restrict__ wq,
         const float* __restrict__ bias, float* __restrict__ out,
         int N, int Cin, int Hin, int Win, int Cout, int Hout, int Wout,
         int pad, int relu, int cotiles, int chunks, int ntiles) {
    constexpr int K2 = K * K;
    constexpr int IH = 3 * STRIDE + K;
    constexpr int IW = 31 * STRIDE + K;

    __shared__ float s_in[16][IH * IW];

    const int tid = threadIdx.x;
    const int lane = tid & 31;
    const int wm = tid >> 5;

    const int bx = blockIdx.x, by = blockIdx.y;
    const int n = blockIdx.z / cotiles;
    const int co0 = (blockIdx.z % cotiles) * 32;

    const int ix0 = bx * 32 * STRIDE - pad;
    const int iy0 = by * 4 * STRIDE - pad;

    const int y = wm >> 1;                   // constant y-row of this m-tile
    const int r = lane >> 2;
    const int xA = ((wm & 1) << 4) + r;      // pixel x for rows r / r+8 -> xA, xA+8
    const int c0 = (lane & 3) * 2;

    float acc[4][4];
#pragma unroll
    for (int i = 0; i < 4; i++)
#pragma unroll
        for (int j = 0; j < 4; j++) acc[i][j] = 0.0f;

    const size_t in_n = (size_t)n * Cin * Hin * Win;

    for (int chunk = 0; chunk < chunks; chunk++) {
        // stage 16 channels
        for (int i = tid; i < 16 * IH * IW; i += 256) {
            int cs = i / (IH * IW);
            int rem = i - cs * (IH * IW);
            int rr = rem / IW, cc = rem - rr * IW;
            int gy = iy0 + rr, gx = ix0 + cc;
            int ci = chunk * 16 + cs;
            float v = 0.0f;
            if (ci < Cin && (unsigned)gy < (unsigned)Hin && (unsigned)gx < (unsigned)Win)
                v = __ldg(in + in_n + (size_t)ci * Hin * Win + (size_t)gy * Win + gx);
            s_in[cs][rem] = v;
        }
        __syncthreads();

#pragma unroll 1
        for (int tl = 0; tl < K2; tl++) {
            float v0[4], v1[4];
#pragma unroll
            for (int j = 0; j < 4; j++) {
                int c = c0 + (j >> 1) * 8 + (j & 1);
                int k = tl * 16 + c;
                int cs = k / K2, kk = k - cs * K2;
                int kh = kk / K, kw = kk - kh * K;
                int ro = (y * STRIDE + kh) * IW + kw;
                v0[j] = s_in[cs][ro + xA * STRIDE];
                v1[j] = s_in[cs][ro + (xA + 8) * STRIDE];
            }
            float h00 = bhi(v0[0]), h01 = bhi(v0[1]), h02 = bhi(v0[2]), h03 = bhi(v0[3]);
            float h10 = bhi(v1[0]), h11 = bhi(v1[1]), h12 = bhi(v1[2]), h13 = bhi(v1[3]);
            unsigned ahi[4], alo[4];
            ahi[0] = pk(h00, h01); ahi[1] = pk(h10, h11);
            ahi[2] = pk(h02, h03); ahi[3] = pk(h12, h13);
            alo[0] = pk(v0[0] - h00, v0[1] - h01);
            alo[1] = pk(v1[0] - h10, v1[1] - h11);
            alo[2] = pk(v0[2] - h02, v0[3] - h03);
            alo[3] = pk(v1[2] - h12, v1[3] - h13);

            int tg = chunk * K2 + tl;
            const uint4* wrow = wq + ((size_t)tg * ntiles + (co0 >> 3)) * 32 + lane;
#pragma unroll
            for (int nt = 0; nt < 4; nt++) {
                uint4 wv = __ldg(wrow + nt * 32);
                MMA(acc[nt], ahi, wv.x, wv.y);   // hi*hi
                MMA(acc[nt], ahi, wv.z, wv.w);   // hi*lo
                MMA(acc[nt], alo, wv.x, wv.y);   // lo*hi
            }
        }
        __syncthreads();
    }

    // store
    const int oy = by * 4 + y;
    if (oy >= Hout) return;
#pragma unroll
    for (int half = 0; half < 2; half++) {
        int ox = bx * 32 + xA + half * 8;
        if (ox >= Wout) continue;
#pragma unroll
        for (int nt = 0; nt < 4; nt++) {
#pragma unroll
            for (int e = 0; e < 2; e++) {
                int co = co0 + nt * 8 + c0 + e;
                if (co >= Cout) continue;
                float v = acc[nt][half * 2 + e];
                if (bias) v += __ldg(bias + co);
                if (relu) v = fmaxf(v, 0.0f);
                out[(((size_t)n * Cout + co) * Hout + oy) * Wout + ox] = v;
            }
        }
    }
}

// ---------------- scalar weight transpose (K=7 path) -------------------------
__global__ void wtrans_kernel(const float* __restrict__ wt, float* __restrict__ wbuf,
                              int Cin, int Cout, int Co_pad, int K2, int total) {
    int idx = blockIdx.x * blockDim.x + threadIdx.x;
    if (idx >= total) return;
    int co = idx % Co_pad;
    int t = idx / Co_pad;
    int kk = t % K2;
    int ci = t / K2;
    wbuf[idx] = (co < Cout) ? __ldg(wt + ((size_t)co * Cin + ci) * K2 + kk) : 0.0f;
}

// ---------------- scalar conv (K=7 only) -------------------------------------
template <int K, int STRIDE>
__global__ void conv_tiled2(const float* __restrict__ in, const float* __restrict__ wbuf,
                            const float* __restrict__ bias, float* __restrict__ out,
                            int N, int Cin, int Hin, int Win,
                            int Cout, int Co_pad, int Hout, int Wout,
                            int pad, int relu, int cotiles) {
    constexpr int K2 = K * K;
    constexpr int IH = 3 * STRIDE + K;
    constexpr int IW = 31 * STRIDE + K;

    __shared__ float s_in[IH * IW];
    __shared__ float4 s_w[K2 * 8];

    const int tid = threadIdx.x;
    const int tx = tid & 15;
    const int ty = (tid >> 4) & 1;
    const int tc = tid >> 5;

    const int bx = blockIdx.x, by = blockIdx.y;
    const int n   = blockIdx.z / cotiles;
    const int co0 = (blockIdx.z % cotiles) * 32;

    const int ix0 = bx * 32 * STRIDE - pad;
    const int iy0 = by * 4 * STRIDE - pad;

    float acc[2][2][4] = {};
    const size_t in_n = (size_t)n * Cin * Hin * Win;

    for (int ci = 0; ci < Cin; ci++) {
        __syncthreads();
        const float* ip = in + in_n + (size_t)ci * Hin * Win;
#pragma unroll 2
        for (int i = tid; i < IH * IW; i += 256) {
            int r = i / IW, c = i - r * IW;
            int gy = iy0 + r, gx = ix0 + c;
            float v = 0.0f;
            if ((unsigned)gy < (unsigned)Hin && (unsigned)gx < (unsigned)Win)
                v = __ldg(ip + (size_t)gy * Win + gx);
            s_in[i] = v;
        }
        const float* wp = wbuf + (size_t)ci * K2 * Co_pad + co0;
#pragma unroll 2
        for (int i = tid; i < K2 * 32; i += 256) {
            int kk = i >> 5, c = i & 31;
            ((float*)s_w)[i] = __ldg(wp + kk * Co_pad + c);
        }
        __syncthreads();

#pragma unroll
        for (int kh = 0; kh < K; kh++) {
#pragma unroll
            for (int kw = 0; kw < K; kw++) {
                float4 w = s_w[(kh * K + kw) * 8 + tc];
                float iv[2][2];
#pragma unroll
                for (int yy = 0; yy < 2; yy++)
#pragma unroll
                    for (int xx = 0; xx < 2; xx++)
                        iv[yy][xx] = s_in[((2 * ty + yy) * STRIDE + kh) * IW
                                          + (2 * tx + xx) * STRIDE + kw];
#pragma unroll
                for (int yy = 0; yy < 2; yy++)
#pragma unroll
                    for (int xx = 0; xx < 2; xx++) {
                        acc[yy][xx][0] = fmaf(iv[yy][xx], w.x, acc[yy][xx][0]);
                        acc[yy][xx][1] = fmaf(iv[yy][xx], w.y, acc[yy][xx][1]);
                        acc[yy][xx][2] = fmaf(iv[yy][xx], w.z, acc[yy][xx][2]);
                        acc[yy][xx][3] = fmaf(iv[yy][xx], w.w, acc[yy][xx][3]);
                    }
            }
        }
    }

    const int ox = bx * 32 + 2 * tx;
    if (ox >= Wout) return;
#pragma unroll
    for (int c = 0; c < 4; c++) {
        int co = co0 + tc * 4 + c;
        if (co >= Cout) continue;
        float bv = bias ? __ldg(bias + co) : 0.0f;
#pragma unroll
        for (int yy = 0; yy < 2; yy++) {
            int oy = by * 4 + 2 * ty + yy;
            if (oy >= Hout) continue;
            float v0 = acc[yy][0][c] + bv;
            float v1 = acc[yy][1][c] + bv;
            if (relu) { v0 = fmaxf(v0, 0.0f); v1 = fmaxf(v1, 0.0f); }
            *(float2*)(out + (((size_t)n * Cout + co) * Hout + oy) * Wout + ox)
                = make_float2(v0, v1);
        }
    }
}

// ---------------- patch extraction -------------------------------------------
__global__ void extract_patches_all(const float* __restrict__ fmbase, float* __restrict__ patches,
                                    int C, int F, int L) {
    int idx = blockIdx.x * blockDim.x + threadIdx.x;
    int total = NB * NP * C * 576;
    if (idx >= total) return;
    int ox = idx % 24;
    int oy = (idx / 24) % 24;
    int c = (idx / 576) % C;
    int p = (idx / (576 * C)) % NP;
    int b = idx / (576 * C * NP);
    int PH = g_PH[b][L], PW = g_PW[b][L];
    if (oy >= PH || ox >= PW) return;
    int top = g_tl[b][L][p][0], left = g_tl[b][L][p][1];
    int h = g_crop[b][L][p][0], w = g_crop[b][L][p][1];

    float sy = ((float)oy + 0.5f) * ((float)h / (float)PH) - 0.5f;
    if (sy < 0.0f) sy = 0.0f;
    float sx = ((float)ox + 0.5f) * ((float)w / (float)PW) - 0.5f;
    if (sx < 0.0f) sx = 0.0f;
    int y0 = (int)sy; float ty = sy - (float)y0;
    int x0 = (int)sx; float tx = sx - (float)x0;
    if (y0 > h - 1) { y0 = h - 1; ty = 0.0f; }
    if (x0 > w - 1) { x0 = w - 1; tx = 0.0f; }
    int y1 = min(y0 + 1, h - 1);
    int x1 = min(x0 + 1, w - 1);

    const float* base = fmbase + (size_t)b * C * F * F + ((size_t)c * F + top) * F + left;
    float v00 = base[y0 * F + x0], v01 = base[y0 * F + x1];
    float v10 = base[y1 * F + x0], v11 = base[y1 * F + x1];
    float val = v00 * (1.0f - ty) * (1.0f - tx) + v01 * (1.0f - ty) * tx
              + v10 * ty * (1.0f - tx) + v11 * ty * tx;
    patches[((size_t)((b * NP + p) * C + c)) * 576 + oy * 24 + ox] = val;
}

__global__ void resize_pf_all(const float* __restrict__ patches, float* __restrict__ pf,
                              int C, int L) {
    int idx = blockIdx.x * blockDim.x + threadIdx.x;
    int total = NB * 3 * NP * C * 1024;
    if (idx >= total) return;
    int ox = idx & 31;
    int oy = (idx >> 5) & 31;
    int c = (idx >> 10) % C;
    int rest = idx / (1024 * C);
    int p = rest % NP;
    int s = (rest / NP) % 3;
    int b = rest / (NP * 3);

    int PHs = g_PHs[b][L][s], PWs = g_PWs[b][L][s];
    if (oy >= PHs || ox >= PWs) return;
    int PH = g_PH[b][L], PW = g_PW[b][L];

    float sy = ((float)oy + 0.5f) * ((float)PH / (float)PHs) - 0.5f;
    if (sy < 0.0f) sy = 0.0f;
    float sx = ((float)ox + 0.5f) * ((float)PW / (float)PWs) - 0.5f;
    if (sx < 0.0f) sx = 0.0f;
    int y0 = (int)sy; float ty = sy - (float)y0;
    int x0 = (int)sx; float tx = sx - (float)x0;
    if (y0 > PH - 1) { y0 = PH - 1; ty = 0.0f; }
    if (x0 > PW - 1) { x0 = PW - 1; tx = 0.0f; }
    int y1 = min(y0 + 1, PH - 1);
    int x1 = min(x0 + 1, PW - 1);

    const float* base = patches + ((size_t)((b * NP + p) * C + c)) * 576;
    float v00 = base[y0 * 24 + x0], v01 = base[y0 * 24 + x1];
    float v10 = base[y1 * 24 + x0], v11 = base[y1 * 24 + x1];
    float val = v00 * (1.0f - ty) * (1.0f - tx) + v01 * (1.0f - ty) * tx
              + v10 * ty * (1.0f - tx) + v11 * ty * tx;
    pf[((size_t)(((b * 3 + s) * NP + p) * C + c) << 10) + oy * 32 + ox] = val;
}

__global__ void zero_kernel(float* __restrict__ buf, int n) {
    int idx = blockIdx.x * blockDim.x + threadIdx.x;
    if (idx < n) buf[idx] = 0.0f;
}

// ---------------- tiled correlation ------------------------------------------
__global__ void __launch_bounds__(256)
sim_tiled(const float* __restrict__ fmbase, const float* __restrict__ pf,
          float* __restrict__ simtmp, int C, int F, int L, int nchunks, int cpc) {
    __shared__ float s_fm[63 * 64];
    __shared__ float s_pf[3][16 * 32];

    const int tid = threadIdx.x;
    const int tx = tid & 15, ty = tid >> 4;

    int chunk = blockIdx.x % nchunks;
    int bs = blockIdx.x / nchunks;
    int b = bs / 3, s = bs % 3;

    int PHs = g_PHs[b][L][s], PWs = g_PWs[b][L][s];
    int padT = PHs >> 1, padL = PWs >> 1;

    const int FF = F * F;
    const float* fm = fmbase + (size_t)b * C * FF;
    const float* pfb = pf + ((size_t)(bs * NP) * C << 10);
    int c0 = chunk * cpc;

    float acc[3][3][3];
#pragma unroll
    for (int p = 0; p < 3; p++)
#pragma unroll
        for (int ry = 0; ry < 3; ry++)
#pragma unroll
            for (int rx = 0; rx < 3; rx++) acc[p][ry][rx] = 0.0f;

    const int iy0 = -padT, ix0 = -padL;
    const int pfrows = PHs * 32;

    for (int c = c0; c < c0 + cpc; c++) {
        __syncthreads();
        const float* fmc = fm + (size_t)c * FF;
        for (int i = tid; i < 63 * 64; i += 256) {
            int r = i >> 6, cc = i & 63;
            int gy = iy0 + r, gx = ix0 + cc;
            float v = 0.0f;
            if ((unsigned)gy < (unsigned)F && (unsigned)gx < (unsigned)F)
                v = __ldg(fmc + gy * F + gx);
            s_fm[i] = v;
        }
        for (int i = tid; i < 3 * pfrows; i += 256) {
            int p = i / pfrows;
            int rem = i - p * pfrows;
            s_pf[p][rem] = __ldg(pfb + (((size_t)(p * C + c)) << 10) + rem);
        }
        __syncthreads();

        for (int i = 0; i < PHs; i++) {
            const float* fr = &s_fm[(ty + i) * 64 + tx];
            const float* p0 = &s_pf[0][i * 32];
            const float* p1 = &s_pf[1][i * 32];
            const float* p2 = &s_pf[2][i * 32];
            for (int j = 0; j < PWs; j++) {
                float w0 = p0[j], w1 = p1[j], w2 = p2[j];
                float v[3][3];
#pragma unroll
                for (int ry = 0; ry < 3; ry++)
#pragma unroll
                    for (int rx = 0; rx < 3; rx++)
                        v[ry][rx] = fr[(ry * 16) * 64 + rx * 16 + j];
#pragma unroll
                for (int ry = 0; ry < 3; ry++)
#pragma unroll
                    for (int rx = 0; rx < 3; rx++) {
                        acc[0][ry][rx] = fmaf(v[ry][rx], w0, acc[0][ry][rx]);
                        acc[1][ry][rx] = fmaf(v[ry][rx], w1, acc[1][ry][rx]);
                        acc[2][ry][rx] = fmaf(v[ry][rx], w2, acc[2][ry][rx]);
                    }
            }
        }
    }

#pragma unroll
    for (int p = 0; p < 3; p++) {
        float* dst = simtmp + (size_t)(((b * 2 + L) * 3 + s) * NP + p) * 2304;
#pragma unroll
        for (int ry = 0; ry < 3; ry++) {
            int y = ty + ry * 16;
            if (y >= F) continue;
#pragma unroll
            for (int rx = 0; rx < 3; rx++) {
                int x = tx + rx * 16;
                if (x >= F) continue;
                atomicAdd(dst + y * F + x, acc[p][ry][rx]);
            }
        }
    }
}

__global__ void sim_resize_all(const float* __restrict__ simtmp, float* __restrict__ sims) {
    int idx = blockIdx.x * blockDim.x + threadIdx.x;
    int total = NB * 2 * 3 * NP * 2304;
    if (idx >= total) return;
    int x = idx % 48;
    int y = (idx / 48) % 48;
    int p = (idx / 2304) % NP;
    int s = (idx / (2304 * NP)) % 3;
    int L = (idx / (2304 * NP * 3)) % 2;
    int b = idx / (2304 * NP * 3 * 2);
    int F = L ? 24 : 48;

    float sy = ((float)y + 0.5f) * ((float)F / 48.0f) - 0.5f;
    if (sy < 0.0f) sy = 0.0f;
    float sx = ((float)x + 0.5f) * ((float)F / 48.0f) - 0.5f;
    if (sx < 0.0f) sx = 0.0f;
    int y0 = (int)sy; float ty = sy - (float)y0;
    int x0 = (int)sx; float tx = sx - (float)x0;
    if (y0 > F - 1) { y0 = F - 1; ty = 0.0f; }
    if (x0 > F - 1) { x0 = F - 1; tx = 0.0f; }
    int y1 = min(y0 + 1, F - 1);
    int x1 = min(x0 + 1, F - 1);

    const float* base = simtmp + (size_t)(((b * 2 + L) * 3 + s) * NP + p) * 2304;
    float v00 = base[y0 * F + x0], v01 = base[y0 * F + x1];
    float v10 = base[y1 * F + x0], v11 = base[y1 * F + x1];
    float val = v00 * (1.0f - ty) * (1.0f - tx) + v01 * (1.0f - ty) * tx
              + v10 * ty * (1.0f - tx) + v11 * ty * tx;
    int ch = L * 3 + s;
    sims[((size_t)(b * NP + p) * 6 + ch) * 2304 + y * 48 + x] = val;
}

// ---------------- align-corners 2x bilinear upsample ------------------------
__global__ void upsample_kernel(const float* __restrict__ in, float* __restrict__ out,
                                int NC, int h, int w) {
    int H = 2 * h, W = 2 * w;
    int idx = blockIdx.x * blockDim.x + threadIdx.x;
    int total = NC * H * W;
    if (idx >= total) return;
    int ox = idx % W;
    int oy = (idx / W) % H;
    int nc = idx / (H * W);

    float stepy = (float)(h - 1) / (float)(H - 1);
    float stepx = (float)(w - 1) / (float)(W - 1);
    float py = (float)oy * stepy;
    float px = (float)ox * stepx;
    int y0 = (int)py; float ty = py - (float)y0;
    int x0 = (int)px; float tx = px - (float)x0;
    if (y0 > h - 1) { y0 = h - 1; ty = 0.0f; }
    if (x0 > w - 1) { x0 = w - 1; tx = 0.0f; }
    int y1 = min(y0 + 1, h - 1);
    int x1 = min(x0 + 1, w - 1);

    const float* ib = in + (size_t)nc * h * w;
    float v00 = ib[y0 * w + x0], v01 = ib[y0 * w + x1];
    float v10 = ib[y1 * w + x0], v11 = ib[y1 * w + x1];
    out[idx] = v00 * (1.0f - ty) * (1.0f - tx) + v01 * (1.0f - ty) * tx
             + v10 * ty * (1.0f - tx) + v11 * ty * tx;
}

// ---------------- fused rw5 + relu + max over P ------------------------------
__global__ void tail_kernel(const float* __restrict__ r4, const float* __restrict__ w5,
                            const float* __restrict__ b5, float* __restrict__ out) {
    __shared__ float sw[32];
    if (threadIdx.x < 32) sw[threadIdx.x] = __ldg(w5 + threadIdx.x);
    __syncthreads();
    const int HW = 384 * 384;
    int idx = blockIdx.x * blockDim.x + threadIdx.x;
    if (idx >= NB * HW) return;
    int b = idx / HW;
    int r = idx % HW;
    float bv = __ldg(b5);
    float m = -1e30f;
#pragma unroll
    for (int p = 0; p < NP; p++) {
        const float* base = r4 + ((size_t)(b * NP + p) * 32) * HW + r;
        float s = bv;
#pragma unroll
        for (int c = 0; c < 32; c++)
            s = fmaf(__ldg(base + (size_t)c * HW), sw[c], s);
        s = fmaxf(s, 0.0f);
        m = fmaxf(m, s);
    }
    out[idx] = m;
}

// ---------------- host-side launch helpers ----------------------------------
static inline int cdiv(int a, int b) { return (a + b - 1) / b; }

static float* s_wbuf = nullptr;
static uint4* s_wq = nullptr;

// mma path: K in {1,3,5}, Cout % 32 == 0
static void run_conv_mma(const float* in, const float* w, const float* b, float* out,
                         int N, int Cin, int Hin, int Win, int Cout,
                         int K, int stride, int pad, bool relu) {
    int Hout = (Hin + 2 * pad - K) / stride + 1;
    int Wout = (Win + 2 * pad - K) / stride + 1;
    int K2 = K * K;
    int chunks = cdiv(Cin, 16);
    int ksteps = chunks * K2;          // total k16 steps
    int cotiles = Cout / 32;
    int ntiles = cotiles * 4;

    int wtotal = ksteps * ntiles * 32;
    wq_kernel<<<cdiv(wtotal, 256), 256>>>(w, s_wq, Cin, Cout, K2, ntiles, wtotal);

    dim3 grid(cdiv(Wout, 32), cdiv(Hout, 4), N * cotiles);
    int rl = relu ? 1 : 0;
    if (stride == 2) {
        conv_mma<3, 2><<<grid, 256>>>(in, s_wq, b, out, N, Cin, Hin, Win, Cout, Hout, Wout, pad, rl, cotiles, chunks, ntiles);
    } else {
        if (K == 5)      conv_mma<5, 1><<<grid, 256>>>(in, s_wq, b, out, N, Cin, Hin, Win, Cout, Hout, Wout, pad, rl, cotiles, chunks, ntiles);
        else if (K == 3) conv_mma<3, 1><<<grid, 256>>>(in, s_wq, b, out, N, Cin, Hin, Win, Cout, Hout, Wout, pad, rl, cotiles, chunks, ntiles);
        else             conv_mma<1, 1><<<grid, 256>>>(in, s_wq, b, out, N, Cin, Hin, Win, Cout, Hout, Wout, pad, rl, cotiles, chunks, ntiles);
    }
}

// scalar path (K=7)
static void run_conv_scalar(const float* in, const float* w, const float* b, float* out,
                            int N, int Cin, int Hin, int Win, int Cout,
                            int K, int stride, int pad, bool relu) {
    int Hout = (Hin + 2 * pad - K) / stride + 1;
    int Wout = (Win + 2 * pad - K) / stride + 1;
    int cotiles = cdiv(Cout, 32);
    int Co_pad = cotiles * 32;
    int K2 = K * K;

    int wtotal = Cin * K2 * Co_pad;
    wtrans_kernel<<<cdiv(wtotal, 256), 256>>>(w, s_wbuf, Cin, Cout, Co_pad, K2, wtotal);

    dim3 grid(cdiv(Wout, 32), cdiv(Hout, 4), N * cotiles);
    int rl = relu ? 1 : 0;
    if (stride == 2)
        conv_tiled2<7, 2><<<grid, 256>>>(in, s_wbuf, b, out, N, Cin, Hin, Win, Cout, Co_pad, Hout, Wout, pad, rl, cotiles);
    else
        conv_tiled2<7, 1><<<grid, 256>>>(in, s_wbuf, b, out, N, Cin, Hin, Win, Cout, Co_pad, Hout, Wout, pad, rl, cotiles);
}

extern "C" void kernel_launch(void* const* d_in, const int* in_sizes, int n_in,
                              void* d_out, int out_size) {
    const float* images = (const float*)d_in[0];
    const float* tlbrs  = (const float*)d_in[1];
    const float* fw1 = (const float*)d_in[2];
    const float* fw2 = (const float*)d_in[3];
    const float* fw3 = (const float*)d_in[4];
    const float* fw4 = (const float*)d_in[5];
    const float* rw1 = (const float*)d_in[6];
    const float* rb1 = (const float*)d_in[7];
    const float* rw2 = (const float*)d_in[8];
    const float* rb2 = (const float*)d_in[9];
    const float* rw3 = (const float*)d_in[10];
    const float* rb3 = (const float*)d_in[11];
    const float* rw4 = (const float*)d_in[12];
    const float* rb4 = (const float*)d_in[13];
    const float* rw5 = (const float*)d_in[14];
    const float* rb5 = (const float*)d_in[15];
    float* out = (float*)d_out;

    float *x1, *x2, *f3, *f4, *patches, *pf, *simtmp, *sims;
    float *r1, *u1, *r2, *u2, *r3, *u3, *r4;
    cudaGetSymbolAddress((void**)&x1, g_x1);
    cudaGetSymbolAddress((void**)&x2, g_x2);
    cudaGetSymbolAddress((void**)&f3, g_f3);
    cudaGetSymbolAddress((void**)&f4, g_f4);
    cudaGetSymbolAddress((void**)&patches, g_patches);
    cudaGetSymbolAddress((void**)&pf, g_pf);
    cudaGetSymbolAddress((void**)&simtmp, g_simtmp);
    cudaGetSymbolAddress((void**)&sims, g_sims);
    cudaGetSymbolAddress((void**)&r1, g_r1);
    cudaGetSymbolAddress((void**)&u1, g_u1);
    cudaGetSymbolAddress((void**)&r2, g_r2);
    cudaGetSymbolAddress((void**)&u2, g_u2);
    cudaGetSymbolAddress((void**)&r3, g_r3);
    cudaGetSymbolAddress((void**)&u3, g_u3);
    cudaGetSymbolAddress((void**)&r4, g_r4);
    cudaGetSymbolAddress((void**)&s_wbuf, g_wbuf);
    cudaGetSymbolAddress((void**)&s_wq, g_wq);

    // box metadata
    meta_kernel<<<1, 1>>>(tlbrs);

    // backbone
    run_conv_scalar(images, fw1, nullptr, x1, 2, 3, 384, 384, 64, 7, 2, 3, true);
    run_conv_mma(x1, fw2, nullptr, x2, 2, 64, 192, 192, 256, 3, 2, 1, true);
    run_conv_mma(x2, fw3, nullptr, f3, 2, 256, 96, 96, 512, 3, 2, 1, true);
    run_conv_mma(f3, fw4, nullptr, f4, 2, 512, 48, 48, 1024, 3, 2, 1, true);

    // similarity features (batched)
    const int SIMTMP_N = 2 * 2 * 3 * 3 * 2304;
    zero_kernel<<<cdiv(SIMTMP_N, 256), 256>>>(simtmp, SIMTMP_N);

    {   // L = 0 (f3: C=512, F=48)
        int C = 512, F = 48, L = 0;
        int te = NB * NP * C * 576;
        extract_patches_all<<<cdiv(te, 256), 256>>>(f3, patches, C, F, L);
        int tr = NB * 3 * NP * C * 1024;
        resize_pf_all<<<cdiv(tr, 256), 256>>>(patches, pf, C, L);
        int nchunks = 32, cpc = C / 32;
        sim_tiled<<<6 * nchunks, 256>>>(f3, pf, simtmp, C, F, L, nchunks, cpc);
    }
    {   // L = 1 (f4: C=1024, F=24)
        int C = 1024, F = 24, L = 1;
        int te = NB * NP * C * 576;
        extract_patches_all<<<cdiv(te, 256), 256>>>(f4, patches, C, F, L);
        int tr = NB * 3 * NP * C * 1024;
        resize_pf_all<<<cdiv(tr, 256), 256>>>(patches, pf, C, L);
        int nchunks = 32, cpc = C / 32;
        sim_tiled<<<6 * nchunks, 256>>>(f4, pf, simtmp, C, F, L, nchunks, cpc);
    }
    {
        int ts = NB * 2 * 3 * NP * 2304;
        sim_resize_all<<<cdiv(ts, 256), 256>>>(simtmp, sims);
    }

    // regressor
    run_conv_scalar(sims, rw1, rb1, r1, 6, 6, 48, 48, 196, 7, 1, 3, true);
    upsample_kernel<<<cdiv(6 * 196 * 96 * 96, 256), 256>>>(r1, u1, 6 * 196, 48, 48);
    run_conv_mma(u1, rw2, rb2, r2, 6, 196, 96, 96, 128, 5, 1, 2, true);
    upsample_kernel<<<cdiv(6 * 128 * 192 * 192, 256), 256>>>(r2, u2, 6 * 128, 96, 96);
    run_conv_mma(u2, rw3, rb3, r3, 6, 128, 192, 192, 64, 3, 1, 1, true);
    upsample_kernel<<<cdiv(6 * 64 * 384 * 384, 256), 256>>>(r3, u3, 6 * 64, 192, 192);
    run_conv_mma(u3, rw4, rb4, r4, 6, 64, 384, 384, 32, 1, 1, 0, true);

    tail_kernel<<<cdiv(NB * 384 * 384, 256), 256>>>(r4, rw5, rb5, out);
}

// round 9
// speedup vs baseline: 2.4601x; 1.2634x over previous
#include <cuda_runtime.h>
#include <cuda_bf16.h>
#include <math.h>

// ============================================================================
// FamNet pipeline. bf16 split mma convs (pre-split smem staging) + tiled sims.
// ============================================================================

#define NB 2
#define NP 3

// ---------------- device scratch (no allocations allowed) -------------------
__device__ float g_x1[2 * 64 * 192 * 192];
__device__ float g_x2[2 * 256 * 96 * 96];
__device__ float g_f3[2 * 512 * 48 * 48];
__device__ float g_f4[2 * 1024 * 24 * 24];
__device__ float g_patches[2 * 3 * 1024 * 576];
__device__ float g_pf[2 * 3 * 3 * 1024 * 1024];
__device__ float g_simtmp[2 * 2 * 3 * 3 * 2304];
__device__ float g_sims[2 * 3 * 6 * 48 * 48];
__device__ float g_r1[6 * 196 * 48 * 48];
__device__ float g_u1[6 * 196 * 96 * 96];
__device__ float g_r2[6 * 128 * 96 * 96];
__device__ float g_u2[6 * 128 * 192 * 192];
__device__ float g_r3[6 * 64 * 192 * 192];
__device__ float g_u3[6 * 64 * 384 * 384];
__device__ float g_r4[6 * 32 * 384 * 384];
__device__ float g_wbuf[64 * 49 * 64];                // scalar-path weights (fw1 only)
__device__ uint4 g_wq[1200000];                       // mma-path weights

// ---------------- box / scale metadata --------------------------------------
__device__ int g_tl[2][2][3][2];
__device__ int g_crop[2][2][3][2];
__device__ int g_PH[2][2], g_PW[2][2];
__device__ int g_PHs[2][2][3], g_PWs[2][2][3];

__global__ void meta_kernel(const float* __restrict__ tlbrs) {
    if (threadIdx.x != 0 || blockIdx.x != 0) return;
    const double scales[3] = {1.0, 0.9, 1.1};
    for (int b = 0; b < NB; b++) {
        for (int L = 0; L < 2; L++) {
            int F = (L == 0) ? 48 : 24;
            float inv = (float)F / 384.0f;
            int maxh = 0, maxw = 0;
            for (int p = 0; p < NP; p++) {
                const float* v = tlbrs + (b * NP + p) * 4;
                float sct = v[0] * inv, scl = v[1] * inv;
                float scb = v[2] * inv, scr = v[3] * inv;
                int top = (int)floorf(sct); if (top < 0) top = 0;
                int left = (int)floorf(scl); if (left < 0) left = 0;
                int bot = (int)ceilf(scb) + 1; if (bot > F) bot = F;
                int right = (int)ceilf(scr) + 1; if (right > F) right = F;
                g_tl[b][L][p][0] = top;  g_tl[b][L][p][1] = left;
                g_crop[b][L][p][0] = bot - top;  g_crop[b][L][p][1] = right - left;
                if (bot - top > maxh) maxh = bot - top;
                if (right - left > maxw) maxw = right - left;
            }
            g_PH[b][L] = maxh; g_PW[b][L] = maxw;
            for (int s = 0; s < 3; s++) {
                int ph = (int)ceil((double)maxh * scales[s]);
                int pw = (int)ceil((double)maxw * scales[s]);
                if (ph < 1) ph = maxh;
                if (pw < 1) pw = maxw;
                g_PHs[b][L][s] = ph; g_PWs[b][L][s] = pw;
            }
        }
    }
}

// ---------------- helpers ----------------------------------------------------
__device__ __forceinline__ unsigned pk(float a, float b) {
    unsigned ha = (unsigned)__bfloat16_as_ushort(__float2bfloat16_rn(a));
    unsigned hb = (unsigned)__bfloat16_as_ushort(__float2bfloat16_rn(b));
    return ha | (hb << 16);
}
__device__ __forceinline__ float bhi(float v) {
    return __bfloat162float(__float2bfloat16_rn(v));
}

#define MMA(d, a, bb0, bb1)                                                       \
    asm volatile("mma.sync.aligned.m16n8k16.row.col.f32.bf16.bf16.f32 "           \
                 "{%0,%1,%2,%3},{%4,%5,%6,%7},{%8,%9},{%0,%1,%2,%3};"             \
                 : "+f"(d[0]), "+f"(d[1]), "+f"(d[2]), "+f"(d[3])                 \
                 : "r"(a[0]), "r"(a[1]), "r"(a[2]), "r"(a[3]), "r"(bb0), "r"(bb1))

// ---------------- mma weight transform ---------------------------------------
// k-order: within k16 step t = chunk*K2 + tl, fragment k index kf = channel
// within chunk (tap fixed = tl). wq[t][ntile][lane] = {b0hi,b1hi,b0lo,b1lo}.
__global__ void wq_kernel(const float* __restrict__ wt, uint4* __restrict__ wq,
                          int Cin, int Cout, int K2, int ntiles, int total) {
    int idx = blockIdx.x * blockDim.x + threadIdx.x;
    if (idx >= total) return;
    int lane = idx & 31;
    int nt = (idx >> 5) % ntiles;
    int t = idx / (32 * ntiles);
    int chunk = t / K2, tl = t - chunk * K2;
    int n = nt * 8 + (lane >> 2);
    int kf0 = (lane & 3) * 2;

    float w[4], whi[4];
#pragma unroll
    for (int j = 0; j < 4; j++) {
        int kf = kf0 + (j >> 1) * 8 + (j & 1);
        int ci = chunk * 16 + kf;
        w[j] = (ci < Cin && n < Cout) ? __ldg(wt + ((size_t)n * Cin + ci) * K2 + tl) : 0.0f;
        whi[j] = bhi(w[j]);
    }
    uint4 o;
    o.x = pk(whi[0], whi[1]);
    o.y = pk(whi[2], whi[3]);
    o.z = pk(w[0] - whi[0], w[1] - whi[1]);
    o.w = pk(w[2] - whi[2], w[3] - whi[3]);
    wq[idx] = o;
}

// ---------------- mma conv: 32x4 px x 32 couts -------------------------------
// smem staged as packed bf16 hi/lo channel-pairs; A fragments = raw LDS.32.
template <int K, int STRIDE>
__global__ void __launch_bounds__(256)
conv_mma(const float* __restrict__ in, const uint4* __restrict__ wq,
         const float* __restrict__ bias, float* __restrict__ out,
         int N, int Cin, int Hin, int Win, int Cout, int Hout, int Wout,
         int pad, int relu, int cotiles, int chunks, int ntiles) {
    constexpr int K2 = K * K;
    constexpr int IH = 3 * STRIDE + K;
    constexpr int IW = 31 * STRIDE + K;
    constexpr int NPX = IH * IW;

    __shared__ unsigned s_hi[NPX][8];
    __shared__ unsigned s_lo[NPX][8];

    const int tid = threadIdx.x;
    const int lane = tid & 31;
    const int wm = tid >> 5;

    const int bx = blockIdx.x, by = blockIdx.y;
    const int n = blockIdx.z / cotiles;
    const int co0 = (blockIdx.z % cotiles) * 32;

    const int ix0 = bx * 32 * STRIDE - pad;
    const int iy0 = by * 4 * STRIDE - pad;

    const int y = wm >> 1;
    const int r = lane >> 2;
    const int xA = ((wm & 1) << 4) + r;
    const int pcL = lane & 3;
    const int c0 = pcL * 2;

    float acc[4][4];
#pragma unroll
    for (int i = 0; i < 4; i++)
#pragma unroll
        for (int j = 0; j < 4; j++) acc[i][j] = 0.0f;

    const size_t in_n = (size_t)n * Cin * Hin * Win;
    const size_t HW = (size_t)Hin * Win;

    for (int chunk = 0; chunk < chunks; chunk++) {
        // stage 16 channels as packed bf16 hi/lo pairs (split once)
        for (int i = tid; i < 8 * NPX; i += 256) {
            int pc = i / NPX;
            int rem = i - pc * NPX;
            int rr = rem / IW, cc = rem - rr * IW;
            int gy = iy0 + rr, gx = ix0 + cc;
            int ci0 = chunk * 16 + pc * 2;
            float f0 = 0.0f, f1 = 0.0f;
            if ((unsigned)gy < (unsigned)Hin && (unsigned)gx < (unsigned)Win) {
                const float* p = in + in_n + (size_t)gy * Win + gx;
                if (ci0 < Cin)     f0 = __ldg(p + (size_t)ci0 * HW);
                if (ci0 + 1 < Cin) f1 = __ldg(p + (size_t)(ci0 + 1) * HW);
            }
            float h0 = bhi(f0), h1 = bhi(f1);
            int sw = (pc + rem) & 7;
            s_hi[rem][sw] = pk(h0, h1);
            s_lo[rem][sw] = pk(f0 - h0, f1 - h1);
        }
        __syncthreads();

#pragma unroll 1
        for (int tl = 0; tl < K2; tl++) {
            int kh = tl / K, kw = tl - kh * K;
            int pixA = (y * STRIDE + kh) * IW + kw + xA * STRIDE;
            int pixB = pixA + 8 * STRIDE;

            unsigned ahi[4], alo[4];
            ahi[0] = s_hi[pixA][(pcL + pixA) & 7];
            ahi[1] = s_hi[pixB][(pcL + pixB) & 7];
            ahi[2] = s_hi[pixA][(pcL + 4 + pixA) & 7];
            ahi[3] = s_hi[pixB][(pcL + 4 + pixB) & 7];
            alo[0] = s_lo[pixA][(pcL + pixA) & 7];
            alo[1] = s_lo[pixB][(pcL + pixB) & 7];
            alo[2] = s_lo[pixA][(pcL + 4 + pixA) & 7];
            alo[3] = s_lo[pixB][(pcL + 4 + pixB) & 7];

            int tg = chunk * K2 + tl;
            const uint4* wrow = wq + ((size_t)tg * ntiles + (co0 >> 3)) * 32 + lane;
#pragma unroll
            for (int nt = 0; nt < 4; nt++) {
                uint4 wv = __ldg(wrow + nt * 32);
                MMA(acc[nt], ahi, wv.x, wv.y);   // hi*hi
                MMA(acc[nt], ahi, wv.z, wv.w);   // hi*lo
                MMA(acc[nt], alo, wv.x, wv.y);   // lo*hi
            }
        }
        __syncthreads();
    }

    const int oy = by * 4 + y;
    if (oy >= Hout) return;
#pragma unroll
    for (int half = 0; half < 2; half++) {
        int ox = bx * 32 + xA + half * 8;
        if (ox >= Wout) continue;
#pragma unroll
        for (int nt = 0; nt < 4; nt++) {
#pragma unroll
            for (int e = 0; e < 2; e++) {
                int co = co0 + nt * 8 + c0 + e;
                if (co >= Cout) continue;
                float v = acc[nt][half * 2 + e];
                if (bias) v += __ldg(bias + co);
                if (relu) v = fmaxf(v, 0.0f);
                out[(((size_t)n * Cout + co) * Hout + oy) * Wout + ox] = v;
            }
        }
    }
}

// ---------------- scalar weight transpose (fw1 only) -------------------------
__global__ void wtrans_kernel(const float* __restrict__ wt, float* __restrict__ wbuf,
                              int Cin, int Cout, int Co_pad, int K2, int total) {
    int idx = blockIdx.x * blockDim.x + threadIdx.x;
    if (idx >= total) return;
    int co = idx % Co_pad;
    int t = idx / Co_pad;
    int kk = t % K2;
    int ci = t / K2;
    wbuf[idx] = (co < Cout) ? __ldg(wt + ((size_t)co * Cin + ci) * K2 + kk) : 0.0f;
}

// ---------------- scalar conv (fw1 only: K=7, S=2) ---------------------------
template <int K, int STRIDE>
__global__ void conv_tiled2(const float* __restrict__ in, const float* __restrict__ wbuf,
                            const float* __restrict__ bias, float* __restrict__ out,
                            int N, int Cin, int Hin, int Win,
                            int Cout, int Co_pad, int Hout, int Wout,
                            int pad, int relu, int cotiles) {
    constexpr int K2 = K * K;
    constexpr int IH = 3 * STRIDE + K;
    constexpr int IW = 31 * STRIDE + K;

    __shared__ float s_in[IH * IW];
    __shared__ float4 s_w[K2 * 8];

    const int tid = threadIdx.x;
    const int tx = tid & 15;
    const int ty = (tid >> 4) & 1;
    const int tc = tid >> 5;

    const int bx = blockIdx.x, by = blockIdx.y;
    const int n   = blockIdx.z / cotiles;
    const int co0 = (blockIdx.z % cotiles) * 32;

    const int ix0 = bx * 32 * STRIDE - pad;
    const int iy0 = by * 4 * STRIDE - pad;

    float acc[2][2][4] = {};
    const size_t in_n = (size_t)n * Cin * Hin * Win;

    for (int ci = 0; ci < Cin; ci++) {
        __syncthreads();
        const float* ip = in + in_n + (size_t)ci * Hin * Win;
#pragma unroll 2
        for (int i = tid; i < IH * IW; i += 256) {
            int r = i / IW, c = i - r * IW;
            int gy = iy0 + r, gx = ix0 + c;
            float v = 0.0f;
            if ((unsigned)gy < (unsigned)Hin && (unsigned)gx < (unsigned)Win)
                v = __ldg(ip + (size_t)gy * Win + gx);
            s_in[i] = v;
        }
        const float* wp = wbuf + (size_t)ci * K2 * Co_pad + co0;
#pragma unroll 2
        for (int i = tid; i < K2 * 32; i += 256) {
            int kk = i >> 5, c = i & 31;
            ((float*)s_w)[i] = __ldg(wp + kk * Co_pad + c);
        }
        __syncthreads();

#pragma unroll
        for (int kh = 0; kh < K; kh++) {
#pragma unroll
            for (int kw = 0; kw < K; kw++) {
                float4 w = s_w[(kh * K + kw) * 8 + tc];
                float iv[2][2];
#pragma unroll
                for (int yy = 0; yy < 2; yy++)
#pragma unroll
                    for (int xx = 0; xx < 2; xx++)
                        iv[yy][xx] = s_in[((2 * ty + yy) * STRIDE + kh) * IW
                                          + (2 * tx + xx) * STRIDE + kw];
#pragma unroll
                for (int yy = 0; yy < 2; yy++)
#pragma unroll
                    for (int xx = 0; xx < 2; xx++) {
                        acc[yy][xx][0] = fmaf(iv[yy][xx], w.x, acc[yy][xx][0]);
                        acc[yy][xx][1] = fmaf(iv[yy][xx], w.y, acc[yy][xx][1]);
                        acc[yy][xx][2] = fmaf(iv[yy][xx], w.z, acc[yy][xx][2]);
                        acc[yy][xx][3] = fmaf(iv[yy][xx], w.w, acc[yy][xx][3]);
                    }
            }
        }
    }

    const int ox = bx * 32 + 2 * tx;
    if (ox >= Wout) return;
#pragma unroll
    for (int c = 0; c < 4; c++) {
        int co = co0 + tc * 4 + c;
        if (co >= Cout) continue;
        float bv = bias ? __ldg(bias + co) : 0.0f;
#pragma unroll
        for (int yy = 0; yy < 2; yy++) {
            int oy = by * 4 + 2 * ty + yy;
            if (oy >= Hout) continue;
            float v0 = acc[yy][0][c] + bv;
            float v1 = acc[yy][1][c] + bv;
            if (relu) { v0 = fmaxf(v0, 0.0f); v1 = fmaxf(v1, 0.0f); }
            *(float2*)(out + (((size_t)n * Cout + co) * Hout + oy) * Wout + ox)
                = make_float2(v0, v1);
        }
    }
}

// ---------------- patch extraction -------------------------------------------
__global__ void extract_patches_all(const float* __restrict__ fmbase, float* __restrict__ patches,
                                    int C, int F, int L) {
    int idx = blockIdx.x * blockDim.x + threadIdx.x;
    int total = NB * NP * C * 576;
    if (idx >= total) return;
    int ox = idx % 24;
    int oy = (idx / 24) % 24;
    int c = (idx / 576) % C;
    int p = (idx / (576 * C)) % NP;
    int b = idx / (576 * C * NP);
    int PH = g_PH[b][L], PW = g_PW[b][L];
    if (oy >= PH || ox >= PW) return;
    int top = g_tl[b][L][p][0], left = g_tl[b][L][p][1];
    int h = g_crop[b][L][p][0], w = g_crop[b][L][p][1];

    float sy = ((float)oy + 0.5f) * ((float)h / (float)PH) - 0.5f;
    if (sy < 0.0f) sy = 0.0f;
    float sx = ((float)ox + 0.5f) * ((float)w / (float)PW) - 0.5f;
    if (sx < 0.0f) sx = 0.0f;
    int y0 = (int)sy; float ty = sy - (float)y0;
    int x0 = (int)sx; float tx = sx - (float)x0;
    if (y0 > h - 1) { y0 = h - 1; ty = 0.0f; }
    if (x0 > w - 1) { x0 = w - 1; tx = 0.0f; }
    int y1 = min(y0 + 1, h - 1);
    int x1 = min(x0 + 1, w - 1);

    const float* base = fmbase + (size_t)b * C * F * F + ((size_t)c * F + top) * F + left;
    float v00 = base[y0 * F + x0], v01 = base[y0 * F + x1];
    float v10 = base[y1 * F + x0], v11 = base[y1 * F + x1];
    float val = v00 * (1.0f - ty) * (1.0f - tx) + v01 * (1.0f - ty) * tx
              + v10 * ty * (1.0f - tx) + v11 * ty * tx;
    patches[((size_t)((b * NP + p) * C + c)) * 576 + oy * 24 + ox] = val;
}

__global__ void resize_pf_all(const float* __restrict__ patches, float* __restrict__ pf,
                              int C, int L) {
    int idx = blockIdx.x * blockDim.x + threadIdx.x;
    int total = NB * 3 * NP * C * 1024;
    if (idx >= total) return;
    int ox = idx & 31;
    int oy = (idx >> 5) & 31;
    int c = (idx >> 10) % C;
    int rest = idx / (1024 * C);
    int p = rest % NP;
    int s = (rest / NP) % 3;
    int b = rest / (NP * 3);

    int PHs = g_PHs[b][L][s], PWs = g_PWs[b][L][s];
    if (oy >= PHs || ox >= PWs) return;
    int PH = g_PH[b][L], PW = g_PW[b][L];

    float sy = ((float)oy + 0.5f) * ((float)PH / (float)PHs) - 0.5f;
    if (sy < 0.0f) sy = 0.0f;
    float sx = ((float)ox + 0.5f) * ((float)PW / (float)PWs) - 0.5f;
    if (sx < 0.0f) sx = 0.0f;
    int y0 = (int)sy; float ty = sy - (float)y0;
    int x0 = (int)sx; float tx = sx - (float)x0;
    if (y0 > PH - 1) { y0 = PH - 1; ty = 0.0f; }
    if (x0 > PW - 1) { x0 = PW - 1; tx = 0.0f; }
    int y1 = min(y0 + 1, PH - 1);
    int x1 = min(x0 + 1, PW - 1);

    const float* base = patches + ((size_t)((b * NP + p) * C + c)) * 576;
    float v00 = base[y0 * 24 + x0], v01 = base[y0 * 24 + x1];
    float v10 = base[y1 * 24 + x0], v11 = base[y1 * 24 + x1];
    float val = v00 * (1.0f - ty) * (1.0f - tx) + v01 * (1.0f - ty) * tx
              + v10 * ty * (1.0f - tx) + v11 * ty * tx;
    pf[((size_t)(((b * 3 + s) * NP + p) * C + c) << 10) + oy * 32 + ox] = val;
}

__global__ void zero_kernel(float* __restrict__ buf, int n) {
    int idx = blockIdx.x * blockDim.x + threadIdx.x;
    if (idx < n) buf[idx] = 0.0f;
}

// ---------------- tiled correlation ------------------------------------------
__global__ void __launch_bounds__(256)
sim_tiled(const float* __restrict__ fmbase, const float* __restrict__ pf,
          float* __restrict__ simtmp, int C, int F, int L, int nchunks, int cpc) {
    __shared__ float s_fm[63 * 64];
    __shared__ float s_pf[3][16 * 32];

    const int tid = threadIdx.x;
    const int tx = tid & 15, ty = tid >> 4;

    int chunk = blockIdx.x % nchunks;
    int bs = blockIdx.x / nchunks;
    int b = bs / 3, s = bs % 3;

    int PHs = g_PHs[b][L][s], PWs = g_PWs[b][L][s];
    int padT = PHs >> 1, padL = PWs >> 1;

    const int FF = F * F;
    const float* fm = fmbase + (size_t)b * C * FF;
    const float* pfb = pf + ((size_t)(bs * NP) * C << 10);
    int c0 = chunk * cpc;

    float acc[3][3][3];
#pragma unroll
    for (int p = 0; p < 3; p++)
#pragma unroll
        for (int ry = 0; ry < 3; ry++)
#pragma unroll
            for (int rx = 0; rx < 3; rx++) acc[p][ry][rx] = 0.0f;

    const int iy0 = -padT, ix0 = -padL;
    const int pfrows = PHs * 32;

    for (int c = c0; c < c0 + cpc; c++) {
        __syncthreads();
        const float* fmc = fm + (size_t)c * FF;
        for (int i = tid; i < 63 * 64; i += 256) {
            int r = i >> 6, cc = i & 63;
            int gy = iy0 + r, gx = ix0 + cc;
            float v = 0.0f;
            if ((unsigned)gy < (unsigned)F && (unsigned)gx < (unsigned)F)
                v = __ldg(fmc + gy * F + gx);
            s_fm[i] = v;
        }
        for (int i = tid; i < 3 * pfrows; i += 256) {
            int p = i / pfrows;
            int rem = i - p * pfrows;
            s_pf[p][rem] = __ldg(pfb + (((size_t)(p * C + c)) << 10) + rem);
        }
        __syncthreads();

        for (int i = 0; i < PHs; i++) {
            const float* fr = &s_fm[(ty + i) * 64 + tx];
            const float* p0 = &s_pf[0][i * 32];
            const float* p1 = &s_pf[1][i * 32];
            const float* p2 = &s_pf[2][i * 32];
            for (int j = 0; j < PWs; j++) {
                float w0 = p0[j], w1 = p1[j], w2 = p2[j];
                float v[3][3];
#pragma unroll
                for (int ry = 0; ry < 3; ry++)
#pragma unroll
                    for (int rx = 0; rx < 3; rx++)
                        v[ry][rx] = fr[(ry * 16) * 64 + rx * 16 + j];
#pragma unroll
                for (int ry = 0; ry < 3; ry++)
#pragma unroll
                    for (int rx = 0; rx < 3; rx++) {
                        acc[0][ry][rx] = fmaf(v[ry][rx], w0, acc[0][ry][rx]);
                        acc[1][ry][rx] = fmaf(v[ry][rx], w1, acc[1][ry][rx]);
                        acc[2][ry][rx] = fmaf(v[ry][rx], w2, acc[2][ry][rx]);
                    }
            }
        }
    }

#pragma unroll
    for (int p = 0; p < 3; p++) {
        float* dst = simtmp + (size_t)(((b * 2 + L) * 3 + s) * NP + p) * 2304;
#pragma unroll
        for (int ry = 0; ry < 3; ry++) {
            int y = ty + ry * 16;
            if (y >= F) continue;
#pragma unroll
            for (int rx = 0; rx < 3; rx++) {
                int x = tx + rx * 16;
                if (x >= F) continue;
                atomicAdd(dst + y * F + x, acc[p][ry][rx]);
            }
        }
    }
}

__global__ void sim_resize_all(const float* __restrict__ simtmp, float* __restrict__ sims) {
    int idx = blockIdx.x * blockDim.x + threadIdx.x;
    int total = NB * 2 * 3 * NP * 2304;
    if (idx >= total) return;
    int x = idx % 48;
    int y = (idx / 48) % 48;
    int p = (idx / 2304) % NP;
    int s = (idx / (2304 * NP)) % 3;
    int L = (idx / (2304 * NP * 3)) % 2;
    int b = idx / (2304 * NP * 3 * 2);
    int F = L ? 24 : 48;

    float sy = ((float)y + 0.5f) * ((float)F / 48.0f) - 0.5f;
    if (sy < 0.0f) sy = 0.0f;
    float sx = ((float)x + 0.5f) * ((float)F / 48.0f) - 0.5f;
    if (sx < 0.0f) sx = 0.0f;
    int y0 = (int)sy; float ty = sy - (float)y0;
    int x0 = (int)sx; float tx = sx - (float)x0;
    if (y0 > F - 1) { y0 = F - 1; ty = 0.0f; }
    if (x0 > F - 1) { x0 = F - 1; tx = 0.0f; }
    int y1 = min(y0 + 1, F - 1);
    int x1 = min(x0 + 1, F - 1);

    const float* base = simtmp + (size_t)(((b * 2 + L) * 3 + s) * NP + p) * 2304;
    float v00 = base[y0 * F + x0], v01 = base[y0 * F + x1];
    float v10 = base[y1 * F + x0], v11 = base[y1 * F + x1];
    float val = v00 * (1.0f - ty) * (1.0f - tx) + v01 * (1.0f - ty) * tx
              + v10 * ty * (1.0f - tx) + v11 * ty * tx;
    int ch = L * 3 + s;
    sims[((size_t)(b * NP + p) * 6 + ch) * 2304 + y * 48 + x] = val;
}

// ---------------- align-corners 2x bilinear upsample ------------------------
__global__ void upsample_kernel(const float* __restrict__ in, float* __restrict__ out,
                                int NC, int h, int w) {
    int H = 2 * h, W = 2 * w;
    int idx = blockIdx.x * blockDim.x + threadIdx.x;
    int total = NC * H * W;
    if (idx >= total) return;
    int ox = idx % W;
    int oy = (idx / W) % H;
    int nc = idx / (H * W);

    float stepy = (float)(h - 1) / (float)(H - 1);
    float stepx = (float)(w - 1) / (float)(W - 1);
    float py = (float)oy * stepy;
    float px = (float)ox * stepx;
    int y0 = (int)py; float ty = py - (float)y0;
    int x0 = (int)px; float tx = px - (float)x0;
    if (y0 > h - 1) { y0 = h - 1; ty = 0.0f; }
    if (x0 > w - 1) { x0 = w - 1; tx = 0.0f; }
    int y1 = min(y0 + 1, h - 1);
    int x1 = min(x0 + 1, w - 1);

    const float* ib = in + (size_t)nc * h * w;
    float v00 = ib[y0 * w + x0], v01 = ib[y0 * w + x1];
    float v10 = ib[y1 * w + x0], v11 = ib[y1 * w + x1];
    out[idx] = v00 * (1.0f - ty) * (1.0f - tx) + v01 * (1.0f - ty) * tx
             + v10 * ty * (1.0f - tx) + v11 * ty * tx;
}

// ---------------- fused rw5 + relu + max over P ------------------------------
__global__ void tail_kernel(const float* __restrict__ r4, const float* __restrict__ w5,
                            const float* __restrict__ b5, float* __restrict__ out) {
    __shared__ float sw[32];
    if (threadIdx.x < 32) sw[threadIdx.x] = __ldg(w5 + threadIdx.x);
    __syncthreads();
    const int HW = 384 * 384;
    int idx = blockIdx.x * blockDim.x + threadIdx.x;
    if (idx >= NB * HW) return;
    int b = idx / HW;
    int r = idx % HW;
    float bv = __ldg(b5);
    float m = -1e30f;
#pragma unroll
    for (int p = 0; p < NP; p++) {
        const float* base = r4 + ((size_t)(b * NP + p) * 32) * HW + r;
        float s = bv;
#pragma unroll
        for (int c = 0; c < 32; c++)
            s = fmaf(__ldg(base + (size_t)c * HW), sw[c], s);
        s = fmaxf(s, 0.0f);
        m = fmaxf(m, s);
    }
    out[idx] = m;
}

// ---------------- host-side launch helpers ----------------------------------
static inline int cdiv(int a, int b) { return (a + b - 1) / b; }

static float* s_wbuf = nullptr;
static uint4* s_wq = nullptr;

// mma path: K in {1,3,5,7}
static void run_conv_mma(const float* in, const float* w, const float* b, float* out,
                         int N, int Cin, int Hin, int Win, int Cout,
                         int K, int stride, int pad, bool relu) {
    int Hout = (Hin + 2 * pad - K) / stride + 1;
    int Wout = (Win + 2 * pad - K) / stride + 1;
    int K2 = K * K;
    int chunks = cdiv(Cin, 16);
    int ksteps = chunks * K2;
    int cotiles = cdiv(Cout, 32);
    int ntiles = cotiles * 4;

    int wtotal = ksteps * ntiles * 32;
    wq_kernel<<<cdiv(wtotal, 256), 256>>>(w, s_wq, Cin, Cout, K2, ntiles, wtotal);

    dim3 grid(cdiv(Wout, 32), cdiv(Hout, 4), N * cotiles);
    int rl = relu ? 1 : 0;
    if (stride == 2) {
        conv_mma<3, 2><<<grid, 256>>>(in, s_wq, b, out, N, Cin, Hin, Win, Cout, Hout, Wout, pad, rl, cotiles, chunks, ntiles);
    } else {
        if (K == 7)      conv_mma<7, 1><<<grid, 256>>>(in, s_wq, b, out, N, Cin, Hin, Win, Cout, Hout, Wout, pad, rl, cotiles, chunks, ntiles);
        else if (K == 5) conv_mma<5, 1><<<grid, 256>>>(in, s_wq, b, out, N, Cin, Hin, Win, Cout, Hout, Wout, pad, rl, cotiles, chunks, ntiles);
        else if (K == 3) conv_mma<3, 1><<<grid, 256>>>(in, s_wq, b, out, N, Cin, Hin, Win, Cout, Hout, Wout, pad, rl, cotiles, chunks, ntiles);
        else             conv_mma<1, 1><<<grid, 256>>>(in, s_wq, b, out, N, Cin, Hin, Win, Cout, Hout, Wout, pad, rl, cotiles, chunks, ntiles);
    }
}

// scalar path (fw1 only)
static void run_conv_scalar(const float* in, const float* w, const float* b, float* out,
                            int N, int Cin, int Hin, int Win, int Cout,
                            int K, int stride, int pad, bool relu) {
    int Hout = (Hin + 2 * pad - K) / stride + 1;
    int Wout = (Win + 2 * pad - K) / stride + 1;
    int cotiles = cdiv(Cout, 32);
    int Co_pad = cotiles * 32;
    int K2 = K * K;

    int wtotal = Cin * K2 * Co_pad;
    wtrans_kernel<<<cdiv(wtotal, 256), 256>>>(w, s_wbuf, Cin, Cout, Co_pad, K2, wtotal);

    dim3 grid(cdiv(Wout, 32), cdiv(Hout, 4), N * cotiles);
    int rl = relu ? 1 : 0;
    conv_tiled2<7, 2><<<grid, 256>>>(in, s_wbuf, b, out, N, Cin, Hin, Win, Cout, Co_pad, Hout, Wout, pad, rl, cotiles);
}

extern "C" void kernel_launch(void* const* d_in, const int* in_sizes, int n_in,
                              void* d_out, int out_size) {
    const float* images = (const float*)d_in[0];
    const float* tlbrs  = (const float*)d_in[1];
    const float* fw1 = (const float*)d_in[2];
    const float* fw2 = (const float*)d_in[3];
    const float* fw3 = (const float*)d_in[4];
    const float* fw4 = (const float*)d_in[5];
    const float* rw1 = (const float*)d_in[6];
    const float* rb1 = (const float*)d_in[7];
    const float* rw2 = (const float*)d_in[8];
    const float* rb2 = (const float*)d_in[9];
    const float* rw3 = (const float*)d_in[10];
    const float* rb3 = (const float*)d_in[11];
    const float* rw4 = (const float*)d_in[12];
    const float* rb4 = (const float*)d_in[13];
    const float* rw5 = (const float*)d_in[14];
    const float* rb5 = (const float*)d_in[15];
    float* out = (float*)d_out;

    float *x1, *x2, *f3, *f4, *patches, *pf, *simtmp, *sims;
    float *r1, *u1, *r2, *u2, *r3, *u3, *r4;
    cudaGetSymbolAddress((void**)&x1, g_x1);
    cudaGetSymbolAddress((void**)&x2, g_x2);
    cudaGetSymbolAddress((void**)&f3, g_f3);
    cudaGetSymbolAddress((void**)&f4, g_f4);
    cudaGetSymbolAddress((void**)&patches, g_patches);
    cudaGetSymbolAddress((void**)&pf, g_pf);
    cudaGetSymbolAddress((void**)&simtmp, g_simtmp);
    cudaGetSymbolAddress((void**)&sims, g_sims);
    cudaGetSymbolAddress((void**)&r1, g_r1);
    cudaGetSymbolAddress((void**)&u1, g_u1);
    cudaGetSymbolAddress((void**)&r2, g_r2);
    cudaGetSymbolAddress((void**)&u2, g_u2);
    cudaGetSymbolAddress((void**)&r3, g_r3);
    cudaGetSymbolAddress((void**)&u3, g_u3);
    cudaGetSymbolAddress((void**)&r4, g_r4);
    cudaGetSymbolAddress((void**)&s_wbuf, g_wbuf);
    cudaGetSymbolAddress((void**)&s_wq, g_wq);

    // box metadata
    meta_kernel<<<1, 1>>>(tlbrs);

    // backbone
    run_conv_scalar(images, fw1, nullptr, x1, 2, 3, 384, 384, 64, 7, 2, 3, true);
    run_conv_mma(x1, fw2, nullptr, x2, 2, 64, 192, 192, 256, 3, 2, 1, true);
    run_conv_mma(x2, fw3, nullptr, f3, 2, 256, 96, 96, 512, 3, 2, 1, true);
    run_conv_mma(f3, fw4, nullptr, f4, 2, 512, 48, 48, 1024, 3, 2, 1, true);

    // similarity features (batched)
    const int SIMTMP_N = 2 * 2 * 3 * 3 * 2304;
    zero_kernel<<<cdiv(SIMTMP_N, 256), 256>>>(simtmp, SIMTMP_N);

    {   // L = 0 (f3: C=512, F=48)
        int C = 512, F = 48, L = 0;
        int te = NB * NP * C * 576;
        extract_patches_all<<<cdiv(te, 256), 256>>>(f3, patches, C, F, L);
        int tr = NB * 3 * NP * C * 1024;
        resize_pf_all<<<cdiv(tr, 256), 256>>>(patches, pf, C, L);
        int nchunks = 32, cpc = C / 32;
        sim_tiled<<<6 * nchunks, 256>>>(f3, pf, simtmp, C, F, L, nchunks, cpc);
    }
    {   // L = 1 (f4: C=1024, F=24)
        int C = 1024, F = 24, L = 1;
        int te = NB * NP * C * 576;
        extract_patches_all<<<cdiv(te, 256), 256>>>(f4, patches, C, F, L);
        int tr = NB * 3 * NP * C * 1024;
        resize_pf_all<<<cdiv(tr, 256), 256>>>(patches, pf, C, L);
        int nchunks = 32, cpc = C / 32;
        sim_tiled<<<6 * nchunks, 256>>>(f4, pf, simtmp, C, F, L, nchunks, cpc);
    }
    {
        int ts = NB * 2 * 3 * NP * 2304;
        sim_resize_all<<<cdiv(ts, 256), 256>>>(simtmp, sims);
    }

    // regressor
    run_conv_mma(sims, rw1, rb1, r1, 6, 6, 48, 48, 196, 7, 1, 3, true);
    upsample_kernel<<<cdiv(6 * 196 * 96 * 96, 256), 256>>>(r1, u1, 6 * 196, 48, 48);
    run_conv_mma(u1, rw2, rb2, r2, 6, 196, 96, 96, 128, 5, 1, 2, true);
    upsample_kernel<<<cdiv(6 * 128 * 192 * 192, 256), 256>>>(r2, u2, 6 * 128, 96, 96);
    run_conv_mma(u2, rw3, rb3, r3, 6, 128, 192, 192, 64, 3, 1, 1, true);
    upsample_kernel<<<cdiv(6 * 64 * 384 * 384, 256), 256>>>(r3, u3, 6 * 64, 192, 192);
    run_conv_mma(u3, rw4, rb4, r4, 6, 64, 384, 384, 32, 1, 1, 0, true);

    tail_kernel<<<cdiv(NB * 384 * 384, 256), 256>>>(r4, rw5, rb5, out);
}

// round 11
// speedup vs baseline: 2.6219x; 1.0658x over previous
#include <cuda_runtime.h>
#include <cuda_bf16.h>
#include <math.h>

// ============================================================================
// FamNet pipeline. bf16 split mma convs (pre-split staging, 64-cout blocks).
// ============================================================================

#define NB 2
#define NP 3

// ---------------- device scratch (no allocations allowed) -------------------
__device__ float g_x1[2 * 64 * 192 * 192];
__device__ float g_x2[2 * 256 * 96 * 96];
__device__ float g_f3[2 * 512 * 48 * 48];
__device__ float g_f4[2 * 1024 * 24 * 24];
__device__ float g_patches[2 * 3 * 1024 * 576];
__device__ float g_pf[2 * 3 * 3 * 1024 * 1024];
__device__ float g_simtmp[2 * 2 * 3 * 3 * 2304];
__device__ float g_sims[2 * 3 * 6 * 48 * 48];
__device__ float g_r1[6 * 196 * 48 * 48];
__device__ float g_u1[6 * 196 * 96 * 96];
__device__ float g_r2[6 * 128 * 96 * 96];
__device__ float g_u2[6 * 128 * 192 * 192];
__device__ float g_r3[6 * 64 * 192 * 192];
__device__ float g_u3[6 * 64 * 384 * 384];
__device__ float g_r4[6 * 32 * 384 * 384];
__device__ float g_wbuf[64 * 49 * 64];                // scalar-path weights (fw1 only)
__device__ uint4 g_wq[1200000];                       // mma-path weights

// ---------------- box / scale metadata --------------------------------------
__device__ int g_tl[2][2][3][2];
__device__ int g_crop[2][2][3][2];
__device__ int g_PH[2][2], g_PW[2][2];
__device__ int g_PHs[2][2][3], g_PWs[2][2][3];

__global__ void meta_kernel(const float* __restrict__ tlbrs) {
    if (threadIdx.x != 0 || blockIdx.x != 0) return;
    const double scales[3] = {1.0, 0.9, 1.1};
    for (int b = 0; b < NB; b++) {
        for (int L = 0; L < 2; L++) {
            int F = (L == 0) ? 48 : 24;
            float inv = (float)F / 384.0f;
            int maxh = 0, maxw = 0;
            for (int p = 0; p < NP; p++) {
                const float* v = tlbrs + (b * NP + p) * 4;
                float sct = v[0] * inv, scl = v[1] * inv;
                float scb = v[2] * inv, scr = v[3] * inv;
                int top = (int)floorf(sct); if (top < 0) top = 0;
                int left = (int)floorf(scl); if (left < 0) left = 0;
                int bot = (int)ceilf(scb) + 1; if (bot > F) bot = F;
                int right = (int)ceilf(scr) + 1; if (right > F) right = F;
                g_tl[b][L][p][0] = top;  g_tl[b][L][p][1] = left;
                g_crop[b][L][p][0] = bot - top;  g_crop[b][L][p][1] = right - left;
                if (bot - top > maxh) maxh = bot - top;
                if (right - left > maxw) maxw = right - left;
            }
            g_PH[b][L] = maxh; g_PW[b][L] = maxw;
            for (int s = 0; s < 3; s++) {
                int ph = (int)ceil((double)maxh * scales[s]);
                int pw = (int)ceil((double)maxw * scales[s]);
                if (ph < 1) ph = maxh;
                if (pw < 1) pw = maxw;
                g_PHs[b][L][s] = ph; g_PWs[b][L][s] = pw;
            }
        }
    }
}

// ---------------- helpers ----------------------------------------------------
__device__ __forceinline__ unsigned pk(float a, float b) {
    unsigned ha = (unsigned)__bfloat16_as_ushort(__float2bfloat16_rn(a));
    unsigned hb = (unsigned)__bfloat16_as_ushort(__float2bfloat16_rn(b));
    return ha | (hb << 16);
}
__device__ __forceinline__ float bhi(float v) {
    return __bfloat162float(__float2bfloat16_rn(v));
}

#define MMA(d, a, bb0, bb1)                                                       \
    asm volatile("mma.sync.aligned.m16n8k16.row.col.f32.bf16.bf16.f32 "           \
                 "{%0,%1,%2,%3},{%4,%5,%6,%7},{%8,%9},{%0,%1,%2,%3};"             \
                 : "+f"(d[0]), "+f"(d[1]), "+f"(d[2]), "+f"(d[3])                 \
                 : "r"(a[0]), "r"(a[1]), "r"(a[2]), "r"(a[3]), "r"(bb0), "r"(bb1))

// ---------------- mma weight transform ---------------------------------------
__global__ void wq_kernel(const float* __restrict__ wt, uint4* __restrict__ wq,
                          int Cin, int Cout, int K2, int ntiles, int total) {
    int idx = blockIdx.x * blockDim.x + threadIdx.x;
    if (idx >= total) return;
    int lane = idx & 31;
    int nt = (idx >> 5) % ntiles;
    int t = idx / (32 * ntiles);
    int chunk = t / K2, tl = t - chunk * K2;
    int n = nt * 8 + (lane >> 2);
    int kf0 = (lane & 3) * 2;

    float w[4], whi[4];
#pragma unroll
    for (int j = 0; j < 4; j++) {
        int kf = kf0 + (j >> 1) * 8 + (j & 1);
        int ci = chunk * 16 + kf;
        w[j] = (ci < Cin && n < Cout) ? __ldg(wt + ((size_t)n * Cin + ci) * K2 + tl) : 0.0f;
        whi[j] = bhi(w[j]);
    }
    uint4 o;
    o.x = pk(whi[0], whi[1]);
    o.y = pk(whi[2], whi[3]);
    o.z = pk(w[0] - whi[0], w[1] - whi[1]);
    o.w = pk(w[2] - whi[2], w[3] - whi[3]);
    wq[idx] = o;
}

// ---------------- mma conv: 32x4 px x (NT*8) couts ---------------------------
template <int K, int STRIDE, int NT>
__global__ void __launch_bounds__(256)
conv_mma(const float* __restrict__ in, const uint4* __restrict__ wq,
         const float* __restrict__ bias, float* __restrict__ out,
         int N, int Cin, int Hin, int Win, int Cout, int Hout, int Wout,
         int pad, int relu, int cotiles, int chunks, int ntiles) {
    constexpr int K2 = K * K;
    constexpr int IH = 3 * STRIDE + K;
    constexpr int IW = 31 * STRIDE + K;
    constexpr int NPX = IH * IW;

    __shared__ unsigned s_hi[NPX][8];
    __shared__ unsigned s_lo[NPX][8];

    const int tid = threadIdx.x;
    const int lane = tid & 31;
    const int wm = tid >> 5;

    const int bx = blockIdx.x, by = blockIdx.y;
    const int n = blockIdx.z / cotiles;
    const int co0 = (blockIdx.z % cotiles) * (NT * 8);

    const int ix0 = bx * 32 * STRIDE - pad;
    const int iy0 = by * 4 * STRIDE - pad;

    const int y = wm >> 1;
    const int r = lane >> 2;
    const int xA = ((wm & 1) << 4) + r;
    const int pcL = lane & 3;
    const int c0 = pcL * 2;

    float acc[NT][4];
#pragma unroll
    for (int i = 0; i < NT; i++)
#pragma unroll
        for (int j = 0; j < 4; j++) acc[i][j] = 0.0f;

    const size_t in_n = (size_t)n * Cin * Hin * Win;
    const size_t HW = (size_t)Hin * Win;

    for (int chunk = 0; chunk < chunks; chunk++) {
        for (int i = tid; i < 8 * NPX; i += 256) {
            int pc = i / NPX;
            int rem = i - pc * NPX;
            int rr = rem / IW, cc = rem - rr * IW;
            int gy = iy0 + rr, gx = ix0 + cc;
            int ci0 = chunk * 16 + pc * 2;
            float f0 = 0.0f, f1 = 0.0f;
            if ((unsigned)gy < (unsigned)Hin && (unsigned)gx < (unsigned)Win) {
                const float* p = in + in_n + (size_t)gy * Win + gx;
                if (ci0 < Cin)     f0 = __ldg(p + (size_t)ci0 * HW);
                if (ci0 + 1 < Cin) f1 = __ldg(p + (size_t)(ci0 + 1) * HW);
            }
            float h0 = bhi(f0), h1 = bhi(f1);
            int sw = (pc + rem) & 7;
            s_hi[rem][sw] = pk(h0, h1);
            s_lo[rem][sw] = pk(f0 - h0, f1 - h1);
        }
        __syncthreads();

#pragma unroll 1
        for (int tl = 0; tl < K2; tl++) {
            int kh = tl / K, kw = tl - kh * K;
            int pixA = (y * STRIDE + kh) * IW + kw + xA * STRIDE;
            int pixB = pixA + 8 * STRIDE;

            unsigned ahi[4], alo[4];
            ahi[0] = s_hi[pixA][(pcL + pixA) & 7];
            ahi[1] = s_hi[pixB][(pcL + pixB) & 7];
            ahi[2] = s_hi[pixA][(pcL + 4 + pixA) & 7];
            ahi[3] = s_hi[pixB][(pcL + 4 + pixB) & 7];
            alo[0] = s_lo[pixA][(pcL + pixA) & 7];
            alo[1] = s_lo[pixB][(pcL + pixB) & 7];
            alo[2] = s_lo[pixA][(pcL + 4 + pixA) & 7];
            alo[3] = s_lo[pixB][(pcL + 4 + pixB) & 7];

            int tg = chunk * K2 + tl;
            const uint4* wrow = wq + ((size_t)tg * ntiles + (co0 >> 3)) * 32 + lane;
#pragma unroll
            for (int nt = 0; nt < NT; nt++) {
                uint4 wv = __ldg(wrow + nt * 32);
                MMA(acc[nt], ahi, wv.x, wv.y);   // hi*hi
                MMA(acc[nt], ahi, wv.z, wv.w);   // hi*lo
                MMA(acc[nt], alo, wv.x, wv.y);   // lo*hi
            }
        }
        __syncthreads();
    }

    const int oy = by * 4 + y;
    if (oy >= Hout) return;
#pragma unroll
    for (int half = 0; half < 2; half++) {
        int ox = bx * 32 + xA + half * 8;
        if (ox >= Wout) continue;
#pragma unroll
        for (int nt = 0; nt < NT; nt++) {
#pragma unroll
            for (int e = 0; e < 2; e++) {
                int co = co0 + nt * 8 + c0 + e;
                if (co >= Cout) continue;
                float v = acc[nt][half * 2 + e];
                if (bias) v += __ldg(bias + co);
                if (relu) v = fmaxf(v, 0.0f);
                out[(((size_t)n * Cout + co) * Hout + oy) * Wout + ox] = v;
            }
        }
    }
}

// ---------------- scalar weight transpose (fw1 only) -------------------------
__global__ void wtrans_kernel(const float* __restrict__ wt, float* __restrict__ wbuf,
                              int Cin, int Cout, int Co_pad, int K2, int total) {
    int idx = blockIdx.x * blockDim.x + threadIdx.x;
    if (idx >= total) return;
    int co = idx % Co_pad;
    int t = idx / Co_pad;
    int kk = t % K2;
    int ci = t / K2;
    wbuf[idx] = (co < Cout) ? __ldg(wt + ((size_t)co * Cin + ci) * K2 + kk) : 0.0f;
}

// ---------------- scalar conv (fw1 only: K=7, S=2) ---------------------------
template <int K, int STRIDE>
__global__ void conv_tiled2(const float* __restrict__ in, const float* __restrict__ wbuf,
                            const float* __restrict__ bias, float* __restrict__ out,
                            int N, int Cin, int Hin, int Win,
                            int Cout, int Co_pad, int Hout, int Wout,
                            int pad, int relu, int cotiles) {
    constexpr int K2 = K * K;
    constexpr int IH = 3 * STRIDE + K;
    constexpr int IW = 31 * STRIDE + K;

    __shared__ float s_in[IH * IW];
    __shared__ float4 s_w[K2 * 8];

    const int tid = threadIdx.x;
    const int tx = tid & 15;
    const int ty = (tid >> 4) & 1;
    const int tc = tid >> 5;

    const int bx = blockIdx.x, by = blockIdx.y;
    const int n   = blockIdx.z / cotiles;
    const int co0 = (blockIdx.z % cotiles) * 32;

    const int ix0 = bx * 32 * STRIDE - pad;
    const int iy0 = by * 4 * STRIDE - pad;

    float acc[2][2][4] = {};
    const size_t in_n = (size_t)n * Cin * Hin * Win;

    for (int ci = 0; ci < Cin; ci++) {
        __syncthreads();
        const float* ip = in + in_n + (size_t)ci * Hin * Win;
#pragma unroll 2
        for (int i = tid; i < IH * IW; i += 256) {
            int r = i / IW, c = i - r * IW;
            int gy = iy0 + r, gx = ix0 + c;
            float v = 0.0f;
            if ((unsigned)gy < (unsigned)Hin && (unsigned)gx < (unsigned)Win)
                v = __ldg(ip + (size_t)gy * Win + gx);
            s_in[i] = v;
        }
        const float* wp = wbuf + (size_t)ci * K2 * Co_pad + co0;
#pragma unroll 2
        for (int i = tid; i < K2 * 32; i += 256) {
            int kk = i >> 5, c = i & 31;
            ((float*)s_w)[i] = __ldg(wp + kk * Co_pad + c);
        }
        __syncthreads();

#pragma unroll
        for (int kh = 0; kh < K; kh++) {
#pragma unroll
            for (int kw = 0; kw < K; kw++) {
                float4 w = s_w[(kh * K + kw) * 8 + tc];
                float iv[2][2];
#pragma unroll
                for (int yy = 0; yy < 2; yy++)
#pragma unroll
                    for (int xx = 0; xx < 2; xx++)
                        iv[yy][xx] = s_in[((2 * ty + yy) * STRIDE + kh) * IW
                                          + (2 * tx + xx) * STRIDE + kw];
#pragma unroll
                for (int yy = 0; yy < 2; yy++)
#pragma unroll
                    for (int xx = 0; xx < 2; xx++) {
                        acc[yy][xx][0] = fmaf(iv[yy][xx], w.x, acc[yy][xx][0]);
                        acc[yy][xx][1] = fmaf(iv[yy][xx], w.y, acc[yy][xx][1]);
                        acc[yy][xx][2] = fmaf(iv[yy][xx], w.z, acc[yy][xx][2]);
                        acc[yy][xx][3] = fmaf(iv[yy][xx], w.w, acc[yy][xx][3]);
                    }
            }
        }
    }

    const int ox = bx * 32 + 2 * tx;
    if (ox >= Wout) return;
#pragma unroll
    for (int c = 0; c < 4; c++) {
        int co = co0 + tc * 4 + c;
        if (co >= Cout) continue;
        float bv = bias ? __ldg(bias + co) : 0.0f;
#pragma unroll
        for (int yy = 0; yy < 2; yy++) {
            int oy = by * 4 + 2 * ty + yy;
            if (oy >= Hout) continue;
            float v0 = acc[yy][0][c] + bv;
            float v1 = acc[yy][1][c] + bv;
            if (relu) { v0 = fmaxf(v0, 0.0f); v1 = fmaxf(v1, 0.0f); }
            *(float2*)(out + (((size_t)n * Cout + co) * Hout + oy) * Wout + ox)
                = make_float2(v0, v1);
        }
    }
}

// ---------------- patch extraction -------------------------------------------
__global__ void extract_patches_all(const float* __restrict__ fmbase, float* __restrict__ patches,
                                    int C, int F, int L) {
    int idx = blockIdx.x * blockDim.x + threadIdx.x;
    int total = NB * NP * C * 576;
    if (idx >= total) return;
    int ox = idx % 24;
    int oy = (idx / 24) % 24;
    int c = (idx / 576) % C;
    int p = (idx / (576 * C)) % NP;
    int b = idx / (576 * C * NP);
    int PH = g_PH[b][L], PW = g_PW[b][L];
    if (oy >= PH || ox >= PW) return;
    int top = g_tl[b][L][p][0], left = g_tl[b][L][p][1];
    int h = g_crop[b][L][p][0], w = g_crop[b][L][p][1];

    float sy = ((float)oy + 0.5f) * ((float)h / (float)PH) - 0.5f;
    if (sy < 0.0f) sy = 0.0f;
    float sx = ((float)ox + 0.5f) * ((float)w / (float)PW) - 0.5f;
    if (sx < 0.0f) sx = 0.0f;
    int y0 = (int)sy; float ty = sy - (float)y0;
    int x0 = (int)sx; float tx = sx - (float)x0;
    if (y0 > h - 1) { y0 = h - 1; ty = 0.0f; }
    if (x0 > w - 1) { x0 = w - 1; tx = 0.0f; }
    int y1 = min(y0 + 1, h - 1);
    int x1 = min(x0 + 1, w - 1);

    const float* base = fmbase + (size_t)b * C * F * F + ((size_t)c * F + top) * F + left;
    float v00 = base[y0 * F + x0], v01 = base[y0 * F + x1];
    float v10 = base[y1 * F + x0], v11 = base[y1 * F + x1];
    float val = v00 * (1.0f - ty) * (1.0f - tx) + v01 * (1.0f - ty) * tx
              + v10 * ty * (1.0f - tx) + v11 * ty * tx;
    patches[((size_t)((b * NP + p) * C + c)) * 576 + oy * 24 + ox] = val;
}

__global__ void resize_pf_all(const float* __restrict__ patches, float* __restrict__ pf,
                              int C, int L) {
    int idx = blockIdx.x * blockDim.x + threadIdx.x;
    int total = NB * 3 * NP * C * 1024;
    if (idx >= total) return;
    int ox = idx & 31;
    int oy = (idx >> 5) & 31;
    int c = (idx >> 10) % C;
    int rest = idx / (1024 * C);
    int p = rest % NP;
    int s = (rest / NP) % 3;
    int b = rest / (NP * 3);

    int PHs = g_PHs[b][L][s], PWs = g_PWs[b][L][s];
    if (oy >= PHs || ox >= PWs) return;
    int PH = g_PH[b][L], PW = g_PW[b][L];

    float sy = ((float)oy + 0.5f) * ((float)PH / (float)PHs) - 0.5f;
    if (sy < 0.0f) sy = 0.0f;
    float sx = ((float)ox + 0.5f) * ((float)PW / (float)PWs) - 0.5f;
    if (sx < 0.0f) sx = 0.0f;
    int y0 = (int)sy; float ty = sy - (float)y0;
    int x0 = (int)sx; float tx = sx - (float)x0;
    if (y0 > PH - 1) { y0 = PH - 1; ty = 0.0f; }
    if (x0 > PW - 1) { x0 = PW - 1; tx = 0.0f; }
    int y1 = min(y0 + 1, PH - 1);
    int x1 = min(x0 + 1, PW - 1);

    const float* base = patches + ((size_t)((b * NP + p) * C + c)) * 576;
    float v00 = base[y0 * 24 + x0], v01 = base[y0 * 24 + x1];
    float v10 = base[y1 * 24 + x0], v11 = base[y1 * 24 + x1];
    float val = v00 * (1.0f - ty) * (1.0f - tx) + v01 * (1.0f - ty) * tx
              + v10 * ty * (1.0f - tx) + v11 * ty * tx;
    pf[((size_t)(((b * 3 + s) * NP + p) * C + c) << 10) + oy * 32 + ox] = val;
}

__global__ void zero_kernel(float* __restrict__ buf, int n) {
    int idx = blockIdx.x * blockDim.x + threadIdx.x;
    if (idx < n) buf[idx] = 0.0f;
}

// ---------------- tiled correlation ------------------------------------------
__global__ void __launch_bounds__(256)
sim_tiled(const float* __restrict__ fmbase, const float* __restrict__ pf,
          float* __restrict__ simtmp, int C, int F, int L, int nchunks, int cpc) {
    __shared__ float s_fm[63 * 64];
    __shared__ float s_pf[3][16 * 32];

    const int tid = threadIdx.x;
    const int tx = tid & 15, ty = tid >> 4;

    int chunk = blockIdx.x % nchunks;
    int bs = blockIdx.x / nchunks;
    int b = bs / 3, s = bs % 3;

    int PHs = g_PHs[b][L][s], PWs = g_PWs[b][L][s];
    int padT = PHs >> 1, padL = PWs >> 1;

    const int FF = F * F;
    const float* fm = fmbase + (size_t)b * C * FF;
    const float* pfb = pf + ((size_t)(bs * NP) * C << 10);
    int c0 = chunk * cpc;

    float acc[3][3][3];
#pragma unroll
    for (int p = 0; p < 3; p++)
#pragma unroll
        for (int ry = 0; ry < 3; ry++)
#pragma unroll
            for (int rx = 0; rx < 3; rx++) acc[p][ry][rx] = 0.0f;

    const int iy0 = -padT, ix0 = -padL;
    const int pfrows = PHs * 32;

    for (int c = c0; c < c0 + cpc; c++) {
        __syncthreads();
        const float* fmc = fm + (size_t)c * FF;
        for (int i = tid; i < 63 * 64; i += 256) {
            int r = i >> 6, cc = i & 63;
            int gy = iy0 + r, gx = ix0 + cc;
            float v = 0.0f;
            if ((unsigned)gy < (unsigned)F && (unsigned)gx < (unsigned)F)
                v = __ldg(fmc + gy * F + gx);
            s_fm[i] = v;
        }
        for (int i = tid; i < 3 * pfrows; i += 256) {
            int p = i / pfrows;
            int rem = i - p * pfrows;
            s_pf[p][rem] = __ldg(pfb + (((size_t)(p * C + c)) << 10) + rem);
        }
        __syncthreads();

        for (int i = 0; i < PHs; i++) {
            const float* fr = &s_fm[(ty + i) * 64 + tx];
            const float* p0 = &s_pf[0][i * 32];
            const float* p1 = &s_pf[1][i * 32];
            const float* p2 = &s_pf[2][i * 32];
            for (int j = 0; j < PWs; j++) {
                float w0 = p0[j], w1 = p1[j], w2 = p2[j];
                float v[3][3];
#pragma unroll
                for (int ry = 0; ry < 3; ry++)
#pragma unroll
                    for (int rx = 0; rx < 3; rx++)
                        v[ry][rx] = fr[(ry * 16) * 64 + rx * 16 + j];
#pragma unroll
                for (int ry = 0; ry < 3; ry++)
#pragma unroll
                    for (int rx = 0; rx < 3; rx++) {
                        acc[0][ry][rx] = fmaf(v[ry][rx], w0, acc[0][ry][rx]);
                        acc[1][ry][rx] = fmaf(v[ry][rx], w1, acc[1][ry][rx]);
                        acc[2][ry][rx] = fmaf(v[ry][rx], w2, acc[2][ry][rx]);
                    }
            }
        }
    }

#pragma unroll
    for (int p = 0; p < 3; p++) {
        float* dst = simtmp + (size_t)(((b * 2 + L) * 3 + s) * NP + p) * 2304;
#pragma unroll
        for (int ry = 0; ry < 3; ry++) {
            int y = ty + ry * 16;
            if (y >= F) continue;
#pragma unroll
            for (int rx = 0; rx < 3; rx++) {
                int x = tx + rx * 16;
                if (x >= F) continue;
                atomicAdd(dst + y * F + x, acc[p][ry][rx]);
            }
        }
    }
}

__global__ void sim_resize_all(const float* __restrict__ simtmp, float* __restrict__ sims) {
    int idx = blockIdx.x * blockDim.x + threadIdx.x;
    int total = NB * 2 * 3 * NP * 2304;
    if (idx >= total) return;
    int x = idx % 48;
    int y = (idx / 48) % 48;
    int p = (idx / 2304) % NP;
    int s = (idx / (2304 * NP)) % 3;
    int L = (idx / (2304 * NP * 3)) % 2;
    int b = idx / (2304 * NP * 3 * 2);
    int F = L ? 24 : 48;

    float sy = ((float)y + 0.5f) * ((float)F / 48.0f) - 0.5f;
    if (sy < 0.0f) sy = 0.0f;
    float sx = ((float)x + 0.5f) * ((float)F / 48.0f) - 0.5f;
    if (sx < 0.0f) sx = 0.0f;
    int y0 = (int)sy; float ty = sy - (float)y0;
    int x0 = (int)sx; float tx = sx - (float)x0;
    if (y0 > F - 1) { y0 = F - 1; ty = 0.0f; }
    if (x0 > F - 1) { x0 = F - 1; tx = 0.0f; }
    int y1 = min(y0 + 1, F - 1);
    int x1 = min(x0 + 1, F - 1);

    const float* base = simtmp + (size_t)(((b * 2 + L) * 3 + s) * NP + p) * 2304;
    float v00 = base[y0 * F + x0], v01 = base[y0 * F + x1];
    float v10 = base[y1 * F + x0], v11 = base[y1 * F + x1];
    float val = v00 * (1.0f - ty) * (1.0f - tx) + v01 * (1.0f - ty) * tx
              + v10 * ty * (1.0f - tx) + v11 * ty * tx;
    int ch = L * 3 + s;
    sims[((size_t)(b * NP + p) * 6 + ch) * 2304 + y * 48 + x] = val;
}

// ---------------- align-corners 2x bilinear upsample ------------------------
__global__ void upsample_kernel(const float* __restrict__ in, float* __restrict__ out,
                                int NC, int h, int w) {
    int H = 2 * h, W = 2 * w;
    int idx = blockIdx.x * blockDim.x + threadIdx.x;
    int total = NC * H * W;
    if (idx >= total) return;
    int ox = idx % W;
    int oy = (idx / W) % H;
    int nc = idx / (H * W);

    float stepy = (float)(h - 1) / (float)(H - 1);
    float stepx = (float)(w - 1) / (float)(W - 1);
    float py = (float)oy * stepy;
    float px = (float)ox * stepx;
    int y0 = (int)py; float ty = py - (float)y0;
    int x0 = (int)px; float tx = px - (float)x0;
    if (y0 > h - 1) { y0 = h - 1; ty = 0.0f; }
    if (x0 > w - 1) { x0 = w - 1; tx = 0.0f; }
    int y1 = min(y0 + 1, h - 1);
    int x1 = min(x0 + 1, w - 1);

    const float* ib = in + (size_t)nc * h * w;
    float v00 = ib[y0 * w + x0], v01 = ib[y0 * w + x1];
    float v10 = ib[y1 * w + x0], v11 = ib[y1 * w + x1];
    out[idx] = v00 * (1.0f - ty) * (1.0f - tx) + v01 * (1.0f - ty) * tx
             + v10 * ty * (1.0f - tx) + v11 * ty * tx;
}

// ---------------- fused rw5 + relu + max over P ------------------------------
__global__ void tail_kernel(const float* __restrict__ r4, const float* __restrict__ w5,
                            const float* __restrict__ b5, float* __restrict__ out) {
    __shared__ float sw[32];
    if (threadIdx.x < 32) sw[threadIdx.x] = __ldg(w5 + threadIdx.x);
    __syncthreads();
    const int HW = 384 * 384;
    int idx = blockIdx.x * blockDim.x + threadIdx.x;
    if (idx >= NB * HW) return;
    int b = idx / HW;
    int r = idx % HW;
    float bv = __ldg(b5);
    float m = -1e30f;
#pragma unroll
    for (int p = 0; p < NP; p++) {
        const float* base = r4 + ((size_t)(b * NP + p) * 32) * HW + r;
        float s = bv;
#pragma unroll
        for (int c = 0; c < 32; c++)
            s = fmaf(__ldg(base + (size_t)c * HW), sw[c], s);
        s = fmaxf(s, 0.0f);
        m = fmaxf(m, s);
    }
    out[idx] = m;
}

// ---------------- host-side launch helpers ----------------------------------
static inline int cdiv(int a, int b) { return (a + b - 1) / b; }

static float* s_wbuf = nullptr;
static uint4* s_wq = nullptr;

// mma path
static void run_conv_mma(const float* in, const float* w, const float* b, float* out,
                         int N, int Cin, int Hin, int Win, int Cout,
                         int K, int stride, int pad, bool relu) {
    int Hout = (Hin + 2 * pad - K) / stride + 1;
    int Wout = (Win + 2 * pad - K) / stride + 1;
    int K2 = K * K;
    int chunks = cdiv(Cin, 16);
    int ksteps = chunks * K2;

    int NTv = (Cout >= 64) ? 8 : 4;
    int cotiles = cdiv(Cout, NTv * 8);
    int ntiles = cotiles * NTv;

    int wtotal = ksteps * ntiles * 32;
    wq_kernel<<<cdiv(wtotal, 256), 256>>>(w, s_wq, Cin, Cout, K2, ntiles, wtotal);

    dim3 grid(cdiv(Wout, 32), cdiv(Hout, 4), N * cotiles);
    int rl = relu ? 1 : 0;
    if (stride == 2) {
        conv_mma<3, 2, 8><<<grid, 256>>>(in, s_wq, b, out, N, Cin, Hin, Win, Cout, Hout, Wout, pad, rl, cotiles, chunks, ntiles);
    } else if (NTv == 8) {
        if (K == 7)      conv_mma<7, 1, 8><<<grid, 256>>>(in, s_wq, b, out, N, Cin, Hin, Win, Cout, Hout, Wout, pad, rl, cotiles, chunks, ntiles);
        else if (K == 5) conv_mma<5, 1, 8><<<grid, 256>>>(in, s_wq, b, out, N, Cin, Hin, Win, Cout, Hout, Wout, pad, rl, cotiles, chunks, ntiles);
        else if (K == 3) conv_mma<3, 1, 8><<<grid, 256>>>(in, s_wq, b, out, N, Cin, Hin, Win, Cout, Hout, Wout, pad, rl, cotiles, chunks, ntiles);
        else             conv_mma<1, 1, 8><<<grid, 256>>>(in, s_wq, b, out, N, Cin, Hin, Win, Cout, Hout, Wout, pad, rl, cotiles, chunks, ntiles);
    } else {
        conv_mma<1, 1, 4><<<grid, 256>>>(in, s_wq, b, out, N, Cin, Hin, Win, Cout, Hout, Wout, pad, rl, cotiles, chunks, ntiles);
    }
}

// scalar path (fw1 only)
static void run_conv_scalar(const float* in, const float* w, const float* b, float* out,
                            int N, int Cin, int Hin, int Win, int Cout,
                            int K, int stride, int pad, bool relu) {
    int Hout = (Hin + 2 * pad - K) / stride + 1;
    int Wout = (Win + 2 * pad - K) / stride + 1;
    int cotiles = cdiv(Cout, 32);
    int Co_pad = cotiles * 32;
    int K2 = K * K;

    int wtotal = Cin * K2 * Co_pad;
    wtrans_kernel<<<cdiv(wtotal, 256), 256>>>(w, s_wbuf, Cin, Cout, Co_pad, K2, wtotal);

    dim3 grid(cdiv(Wout, 32), cdiv(Hout, 4), N * cotiles);
    int rl = relu ? 1 : 0;
    conv_tiled2<7, 2><<<grid, 256>>>(in, s_wbuf, b, out, N, Cin, Hin, Win, Cout, Co_pad, Hout, Wout, pad, rl, cotiles);
}

extern "C" void kernel_launch(void* const* d_in, const int* in_sizes, int n_in,
                              void* d_out, int out_size) {
    const float* images = (const float*)d_in[0];
    const float* tlbrs  = (const float*)d_in[1];
    const float* fw1 = (const float*)d_in[2];
    const float* fw2 = (const float*)d_in[3];
    const float* fw3 = (const float*)d_in[4];
    const float* fw4 = (const float*)d_in[5];
    const float* rw1 = (const float*)d_in[6];
    const float* rb1 = (const float*)d_in[7];
    const float* rw2 = (const float*)d_in[8];
    const float* rb2 = (const float*)d_in[9];
    const float* rw3 = (const float*)d_in[10];
    const float* rb3 = (const float*)d_in[11];
    const float* rw4 = (const float*)d_in[12];
    const float* rb4 = (const float*)d_in[13];
    const float* rw5 = (const float*)d_in[14];
    const float* rb5 = (const float*)d_in[15];
    float* out = (float*)d_out;

    float *x1, *x2, *f3, *f4, *patches, *pf, *simtmp, *sims;
    float *r1, *u1, *r2, *u2, *r3, *u3, *r4;
    cudaGetSymbolAddress((void**)&x1, g_x1);
    cudaGetSymbolAddress((void**)&x2, g_x2);
    cudaGetSymbolAddress((void**)&f3, g_f3);
    cudaGetSymbolAddress((void**)&f4, g_f4);
    cudaGetSymbolAddress((void**)&patches, g_patches);
    cudaGetSymbolAddress((void**)&pf, g_pf);
    cudaGetSymbolAddress((void**)&simtmp, g_simtmp);
    cudaGetSymbolAddress((void**)&sims, g_sims);
    cudaGetSymbolAddress((void**)&r1, g_r1);
    cudaGetSymbolAddress((void**)&u1, g_u1);
    cudaGetSymbolAddress((void**)&r2, g_r2);
    cudaGetSymbolAddress((void**)&u2, g_u2);
    cudaGetSymbolAddress((void**)&r3, g_r3);
    cudaGetSymbolAddress((void**)&u3, g_u3);
    cudaGetSymbolAddress((void**)&r4, g_r4);
    cudaGetSymbolAddress((void**)&s_wbuf, g_wbuf);
    cudaGetSymbolAddress((void**)&s_wq, g_wq);

    // box metadata
    meta_kernel<<<1, 1>>>(tlbrs);

    // backbone
    run_conv_scalar(images, fw1, nullptr, x1, 2, 3, 384, 384, 64, 7, 2, 3, true);
    run_conv_mma(x1, fw2, nullptr, x2, 2, 64, 192, 192, 256, 3, 2, 1, true);
    run_conv_mma(x2, fw3, nullptr, f3, 2, 256, 96, 96, 512, 3, 2, 1, true);
    run_conv_mma(f3, fw4, nullptr, f4, 2, 512, 48, 48, 1024, 3, 2, 1, true);

    // similarity features (batched)
    const int SIMTMP_N = 2 * 2 * 3 * 3 * 2304;
    zero_kernel<<<cdiv(SIMTMP_N, 256), 256>>>(simtmp, SIMTMP_N);

    {   // L = 0 (f3: C=512, F=48)
        int C = 512, F = 48, L = 0;
        int te = NB * NP * C * 576;
        extract_patches_all<<<cdiv(te, 256), 256>>>(f3, patches, C, F, L);
        int tr = NB * 3 * NP * C * 1024;
        resize_pf_all<<<cdiv(tr, 256), 256>>>(patches, pf, C, L);
        int nchunks = 32, cpc = C / 32;
        sim_tiled<<<6 * nchunks, 256>>>(f3, pf, simtmp, C, F, L, nchunks, cpc);
    }
    {   // L = 1 (f4: C=1024, F=24)
        int C = 1024, F = 24, L = 1;
        int te = NB * NP * C * 576;
        extract_patches_all<<<cdiv(te, 256), 256>>>(f4, patches, C, F, L);
        int tr = NB * 3 * NP * C * 1024;
        resize_pf_all<<<cdiv(tr, 256), 256>>>(patches, pf, C, L);
        int nchunks = 32, cpc = C / 32;
        sim_tiled<<<6 * nchunks, 256>>>(f4, pf, simtmp, C, F, L, nchunks, cpc);
    }
    {
        int ts = NB * 2 * 3 * NP * 2304;
        sim_resize_all<<<cdiv(ts, 256), 256>>>(simtmp, sims);
    }

    // regressor
    run_conv_mma(sims, rw1, rb1, r1, 6, 6, 48, 48, 196, 7, 1, 3, true);
    upsample_kernel<<<cdiv(6 * 196 * 96 * 96, 256), 256>>>(r1, u1, 6 * 196, 48, 48);
    run_conv_mma(u1, rw2, rb2, r2, 6, 196, 96, 96, 128, 5, 1, 2, true);
    upsample_kernel<<<cdiv(6 * 128 * 192 * 192, 256), 256>>>(r2, u2, 6 * 128, 96, 96);
    run_conv_mma(u2, rw3, rb3, r3, 6, 128, 192, 192, 64, 3, 1, 1, true);
    upsample_kernel<<<cdiv(6 * 64 * 384 * 384, 256), 256>>>(r3, u3, 6 * 64, 192, 192);
    run_conv_mma(u3, rw4, rb4, r4, 6, 64, 384, 384, 32, 1, 1, 0, true);

    tail_kernel<<<cdiv(NB * 384 * 384, 256), 256>>>(r4, rw5, rb5, out);
}